// round 4
// baseline (speedup 1.0000x reference)
#include <cuda_runtime.h>
#include <cuda_bf16.h>

#define NN 50000
#define NE 800000
#define IN_DIM 166
#define HID 128
#define BN_EPS 1e-5f

// ---------------- scratch (device globals; float4-typed => 16B-aligned) ----------------
__device__ int    g_is64;           // edge_index dtype flag (1 = int64, 0 = int32)
__device__ int    g_deg[NN];
__device__ int    g_rowptr[NN + 1];
__device__ int    g_cursor[NN];
__device__ int    g_col[NE];
__device__ float4 g_yl[NN * 32];    // [NN,128] fp32
__device__ float4 g_yr[NN * 32];
__device__ float4 g_res[NN * 32];
__device__ float4 g_h1[NN * 32];
__device__ float4 g_h2[NN * 32];
__device__ float4 g_y2[NN];         // [NN,4]
__device__ float4 g_wt[(3 * IN_DIM * HID + 2 * HID * HID) / 4]; // transposed weights

// buffer selectors (device-side pointer resolution)
#define BUF_YL  0
#define BUF_YR  1
#define BUF_RES 2
#define BUF_H1  3
#define BUF_H2  4
__device__ __forceinline__ float4* buf_ptr(int s) {
    switch (s) {
        case BUF_YL:  return g_yl;
        case BUF_YR:  return g_yr;
        case BUF_RES: return g_res;
        case BUF_H1:  return g_h1;
        default:      return g_h2;
    }
}

__device__ __forceinline__ int clamp_node(int v) {
    return v < 0 ? 0 : (v >= NN ? NN - 1 : v);
}

// read edge endpoint i from either-int-width buffer; half=0 -> src, half=1 -> dst
__device__ __forceinline__ int edge_val(const void* ei, int is64, int half, int i) {
    if (is64) {
        long long v = ((const long long*)ei)[(size_t)half * NE + i];
        return clamp_node((int)v);
    } else {
        int v = ((const int*)ei)[(size_t)half * NE + i];
        return clamp_node(v);
    }
}

// ---------------- dtype detection: int64 little-endian small values have 0 hi-words ----------------
__global__ void k_detect(const int* __restrict__ w) {
    if (threadIdx.x == 0 && blockIdx.x == 0) {
        int all_zero = 1;
        for (int t = 0; t < 32; t++) {
            if (w[2 * t + 1] != 0) { all_zero = 0; break; }
        }
        g_is64 = all_zero;
    }
}

// ---------------- CSR build ----------------
__global__ void k_zero_int(int n) {
    int i = blockIdx.x * blockDim.x + threadIdx.x;
    if (i < n) g_deg[i] = 0;
}

__global__ void k_hist(const void* __restrict__ ei) {
    int i = blockIdx.x * blockDim.x + threadIdx.x;
    if (i < NE) {
        int dst = edge_val(ei, g_is64, 1, i);
        atomicAdd(&g_deg[dst], 1);
    }
}

__global__ void k_scan(int n) {
    __shared__ int sm[1024];
    int t = threadIdx.x;
    int chunk = (n + 1023) >> 10;
    int b0 = t * chunk;
    int b1 = min(b0 + chunk, n);
    int s = 0;
    for (int i = b0; i < b1; i++) s += g_deg[i];
    sm[t] = s;
    __syncthreads();
    for (int off = 1; off < 1024; off <<= 1) {
        int v = (t >= off) ? sm[t - off] : 0;
        __syncthreads();
        sm[t] += v;
        __syncthreads();
    }
    int run = sm[t] - s;
    for (int i = b0; i < b1; i++) {
        g_rowptr[i] = run;
        g_cursor[i] = run;
        run += g_deg[i];
    }
    if (t == 1023) g_rowptr[n] = sm[1023];
}

__global__ void k_scatter(const void* __restrict__ ei) {
    int i = blockIdx.x * blockDim.x + threadIdx.x;
    if (i < NE) {
        int is64 = g_is64;
        int src = edge_val(ei, is64, 0, i);
        int dst = edge_val(ei, is64, 1, i);
        int pos = atomicAdd(&g_cursor[dst], 1);
        if (pos >= 0 && pos < NE) g_col[pos] = src;
    }
}

// ---------------- weight transpose: W[N,K] row-major -> g_wt[off + k*N + n] ----------------
__global__ void k_transpose(const float* __restrict__ W, int woff, int Nr, int K) {
    float* wt = reinterpret_cast<float*>(g_wt);
    int i = blockIdx.x * blockDim.x + threadIdx.x;
    if (i < Nr * K) {
        int n = i / K, k = i % K;
        wt[woff + k * Nr + n] = W[i];
    }
}

// ---------------- GEMM: C[M,128] = A[M,K] @ Wt[K,128] (+bias) ----------------
#define BM 128
#define BN 128
#define BK 8
#define AS_STRIDE 132

__global__ __launch_bounds__(256) void k_gemm(
    const float* __restrict__ Ax,   // used when a_sel < 0
    int a_sel,                      // >=0: buffer selector for A
    int woff,                       // offset into g_wt (in floats)
    const float* __restrict__ bias, // may be null
    int out_sel,
    int M, int K)
{
    __shared__ __align__(16) float As[BK * AS_STRIDE];
    __shared__ __align__(16) float Bs[BK * BN];

    const float* A = (a_sel < 0) ? Ax : reinterpret_cast<const float*>(buf_ptr(a_sel));
    float* C = reinterpret_cast<float*>(buf_ptr(out_sel));
    const float* Wt = reinterpret_cast<const float*>(g_wt) + woff;

    int tid = threadIdx.x;
    int tx = tid & 15;   // column quad base: n = tx*4 (+0/ +64)
    int ty = tid >> 4;   // row quad base:    m = ty*4 (+0/ +64)
    int m0 = blockIdx.x * BM;

    float acc[8][8];
#pragma unroll
    for (int i = 0; i < 8; i++)
#pragma unroll
        for (int j = 0; j < 8; j++) acc[i][j] = 0.f;

    int KT = (K + BK - 1) / BK;
    for (int kt = 0; kt < KT; kt++) {
        int k0 = kt * BK;
#pragma unroll
        for (int i = 0; i < 4; i++) {
            int l = tid + i * 256;
            int k = l & 7, m = l >> 3;
            float v = 0.f;
            int gm = m0 + m, gk = k0 + k;
            if (gm < M && gk < K) v = A[(size_t)gm * K + gk];
            As[k * AS_STRIDE + m] = v;
        }
#pragma unroll
        for (int i = 0; i < 4; i++) {
            int l = tid + i * 256;
            int n = l & 127, k = l >> 7;
            float v = 0.f;
            int gk = k0 + k;
            if (gk < K) v = Wt[(size_t)gk * BN + n];
            Bs[k * BN + n] = v;
        }
        __syncthreads();
#pragma unroll
        for (int k = 0; k < BK; k++) {
            float4 a0 = *(const float4*)&As[k * AS_STRIDE + ty * 4];
            float4 a1 = *(const float4*)&As[k * AS_STRIDE + 64 + ty * 4];
            float4 b0 = *(const float4*)&Bs[k * BN + tx * 4];
            float4 b1 = *(const float4*)&Bs[k * BN + 64 + tx * 4];
            float ar[8] = {a0.x, a0.y, a0.z, a0.w, a1.x, a1.y, a1.z, a1.w};
            float br[8] = {b0.x, b0.y, b0.z, b0.w, b1.x, b1.y, b1.z, b1.w};
#pragma unroll
            for (int i = 0; i < 8; i++)
#pragma unroll
                for (int j = 0; j < 8; j++)
                    acc[i][j] = fmaf(ar[i], br[j], acc[i][j]);
        }
        __syncthreads();
    }

    float bv[8] = {0.f, 0.f, 0.f, 0.f, 0.f, 0.f, 0.f, 0.f};
    if (bias != nullptr) {
#pragma unroll
        for (int j = 0; j < 4; j++) bv[j] = bias[tx * 4 + j];
#pragma unroll
        for (int j = 0; j < 4; j++) bv[4 + j] = bias[64 + tx * 4 + j];
    }
#pragma unroll
    for (int i = 0; i < 8; i++) {
        int m = m0 + ((i < 4) ? ty * 4 + i : 64 + ty * 4 + (i - 4));
        if (m >= M) continue;
        *(float4*)&C[(size_t)m * BN + tx * 4] =
            make_float4(acc[i][0] + bv[0], acc[i][1] + bv[1],
                        acc[i][2] + bv[2], acc[i][3] + bv[3]);
        *(float4*)&C[(size_t)m * BN + 64 + tx * 4] =
            make_float4(acc[i][4] + bv[4], acc[i][5] + bv[5],
                        acc[i][6] + bv[6], acc[i][7] + bv[7]);
    }
}

// ---------------- aggregation + BN + ReLU + residual (warp per node) ----------------
__global__ __launch_bounds__(256) void k_agg(
    int res_sel, int out_sel,
    const float* __restrict__ bn_g, const float* __restrict__ bn_b,
    const float* __restrict__ bn_m, const float* __restrict__ bn_v)
{
    const float4* __restrict__ yl  = g_yl;
    const float4* __restrict__ yr  = g_yr;
    const float4* __restrict__ res = buf_ptr(res_sel);
    float4* __restrict__ out       = buf_ptr(out_sel);
    const int* __restrict__ col    = g_col;

    int w = (blockIdx.x * blockDim.x + threadIdx.x) >> 5;
    int lane = threadIdx.x & 31;
    if (w >= NN) return;
    int s0 = g_rowptr[w], s1 = g_rowptr[w + 1];

    float ax = 0.f, ay = 0.f, az = 0.f, aw = 0.f;
    int e = s0;
    for (; e + 1 < s1; e += 2) {
        int sA = clamp_node(col[e]);
        int sB = clamp_node(col[e + 1]);
        float4 vA = yl[sA * 32 + lane];
        float4 vB = yl[sB * 32 + lane];
        ax += vA.x; ay += vA.y; az += vA.z; aw += vA.w;
        ax += vB.x; ay += vB.y; az += vB.z; aw += vB.w;
    }
    if (e < s1) {
        int sA = clamp_node(col[e]);
        float4 vA = yl[sA * 32 + lane];
        ax += vA.x; ay += vA.y; az += vA.z; aw += vA.w;
    }

    int deg = s1 - s0;
    float inv = 1.f / (float)(deg > 1 ? deg : 1);
    float4 r = yr[w * 32 + lane];
    int f = lane * 4;
    float gx = bn_g[f], gy = bn_g[f + 1], gz = bn_g[f + 2], gw = bn_g[f + 3];
    float bx = bn_b[f], by = bn_b[f + 1], bz = bn_b[f + 2], bw = bn_b[f + 3];
    float mx = bn_m[f], my = bn_m[f + 1], mz = bn_m[f + 2], mw = bn_m[f + 3];
    float qx = bn_v[f], qy = bn_v[f + 1], qz = bn_v[f + 2], qw = bn_v[f + 3];
    float4 rr = res[w * 32 + lane];

    float sx = gx * rsqrtf(qx + BN_EPS);
    float sy = gy * rsqrtf(qy + BN_EPS);
    float sz = gz * rsqrtf(qz + BN_EPS);
    float sw = gw * rsqrtf(qw + BN_EPS);

    float vx = (ax * inv + r.x - mx) * sx + bx;
    float vy = (ay * inv + r.y - my) * sy + by;
    float vz = (az * inv + r.z - mz) * sz + bz;
    float vw = (aw * inv + r.w - mw) * sw + bw;
    vx = fmaxf(vx, 0.f) + rr.x;
    vy = fmaxf(vy, 0.f) + rr.y;
    vz = fmaxf(vz, 0.f) + rr.z;
    vw = fmaxf(vw, 0.f) + rr.w;

    out[w * 32 + lane] = make_float4(vx, vy, vz, vw);
}

// ---------------- layer-2 small GEMM: per node, 2 lin_l dots + 2 lin_r dots ----------------
__global__ __launch_bounds__(256) void k_out(
    const float* __restrict__ Wl2, const float* __restrict__ Wr2,
    const float* __restrict__ bl2)
{
    const float4* __restrict__ h = g_h2;
    int w = (blockIdx.x * blockDim.x + threadIdx.x) >> 5;
    int lane = threadIdx.x & 31;
    if (w >= NN) return;
    float4 hv = h[w * 32 + lane];
    int f = lane * 4;
    float a0 = Wl2[f], a1 = Wl2[f + 1], a2 = Wl2[f + 2], a3 = Wl2[f + 3];
    float b0 = Wl2[128 + f], b1 = Wl2[128 + f + 1], b2 = Wl2[128 + f + 2], b3 = Wl2[128 + f + 3];
    float c0 = Wr2[f], c1 = Wr2[f + 1], c2 = Wr2[f + 2], c3 = Wr2[f + 3];
    float e0 = Wr2[128 + f], e1 = Wr2[128 + f + 1], e2 = Wr2[128 + f + 2], e3 = Wr2[128 + f + 3];
    float d0 = hv.x * a0 + hv.y * a1 + hv.z * a2 + hv.w * a3;
    float d1 = hv.x * b0 + hv.y * b1 + hv.z * b2 + hv.w * b3;
    float d2 = hv.x * c0 + hv.y * c1 + hv.z * c2 + hv.w * c3;
    float d3 = hv.x * e0 + hv.y * e1 + hv.z * e2 + hv.w * e3;
#pragma unroll
    for (int off = 16; off; off >>= 1) {
        d0 += __shfl_xor_sync(0xffffffffu, d0, off);
        d1 += __shfl_xor_sync(0xffffffffu, d1, off);
        d2 += __shfl_xor_sync(0xffffffffu, d2, off);
        d3 += __shfl_xor_sync(0xffffffffu, d3, off);
    }
    if (lane == 0) {
        g_y2[w] = make_float4(d0, d1, d2 + bl2[0], d3 + bl2[1]);
    }
}

// ---------------- final: aggregate 2-wide logits + root term ----------------
__global__ void k_final(float* __restrict__ out)
{
    int i = blockIdx.x * blockDim.x + threadIdx.x;
    if (i >= NN) return;
    int s0 = g_rowptr[i], s1 = g_rowptr[i + 1];
    float a0 = 0.f, a1 = 0.f;
    for (int e = s0; e < s1; e++) {
        int s = clamp_node(g_col[e]);
        float4 v = g_y2[s];
        a0 += v.x;
        a1 += v.y;
    }
    int deg = s1 - s0;
    float inv = 1.f / (float)(deg > 1 ? deg : 1);
    float4 self = g_y2[i];
    out[2 * i + 0] = a0 * inv + self.z;
    out[2 * i + 1] = a1 * inv + self.w;
}

// ---------------- launch ----------------
extern "C" void kernel_launch(void* const* d_in, const int* in_sizes, int n_in,
                              void* d_out, int out_size)
{
    const float* x     = (const float*)d_in[0];
    const void*  ei    = (const void*)d_in[1];   // int32 or int64, detected on device
    const float* Wl0   = (const float*)d_in[2];
    const float* bl0   = (const float*)d_in[3];
    const float* Wr0   = (const float*)d_in[4];
    const float* Wl1   = (const float*)d_in[5];
    const float* bl1   = (const float*)d_in[6];
    const float* Wr1   = (const float*)d_in[7];
    const float* Wl2   = (const float*)d_in[8];
    const float* bl2   = (const float*)d_in[9];
    const float* Wr2   = (const float*)d_in[10];
    const float* Wres0 = (const float*)d_in[11];
    const float* bn0_g = (const float*)d_in[12];
    const float* bn0_b = (const float*)d_in[13];
    const float* bn0_m = (const float*)d_in[14];
    const float* bn0_v = (const float*)d_in[15];
    const float* bn1_g = (const float*)d_in[16];
    const float* bn1_b = (const float*)d_in[17];
    const float* bn1_m = (const float*)d_in[18];
    const float* bn1_v = (const float*)d_in[19];

    // transposed weight offsets within g_wt (in floats)
    const int off0l = 0;
    const int off0r = IN_DIM * HID;
    const int off0s = 2 * IN_DIM * HID;
    const int off1l = 3 * IN_DIM * HID;
    const int off1r = 3 * IN_DIM * HID + HID * HID;

    // dtype detection + CSR build
    k_detect<<<1, 32>>>((const int*)ei);
    k_zero_int<<<(NN + 255) / 256, 256>>>(NN);
    k_hist<<<(NE + 255) / 256, 256>>>(ei);
    k_scan<<<1, 1024>>>(NN);
    k_scatter<<<(NE + 255) / 256, 256>>>(ei);

    // weight transposes
    int tw0 = HID * IN_DIM, tw1 = HID * HID;
    k_transpose<<<(tw0 + 255) / 256, 256>>>(Wl0,   off0l, HID, IN_DIM);
    k_transpose<<<(tw0 + 255) / 256, 256>>>(Wr0,   off0r, HID, IN_DIM);
    k_transpose<<<(tw0 + 255) / 256, 256>>>(Wres0, off0s, HID, IN_DIM);
    k_transpose<<<(tw1 + 255) / 256, 256>>>(Wl1,   off1l, HID, HID);
    k_transpose<<<(tw1 + 255) / 256, 256>>>(Wr1,   off1r, HID, HID);

    dim3 gg((NN + BM - 1) / BM, 1);
    int agg_blocks = (NN * 32 + 255) / 256;

    // layer 0: three GEMMs from x, then aggregate + BN + ReLU + residual
    k_gemm<<<gg, 256>>>(x, -1, off0l, nullptr, BUF_YL,  NN, IN_DIM);
    k_gemm<<<gg, 256>>>(x, -1, off0r, bl0,     BUF_YR,  NN, IN_DIM);
    k_gemm<<<gg, 256>>>(x, -1, off0s, nullptr, BUF_RES, NN, IN_DIM);
    k_agg<<<agg_blocks, 256>>>(BUF_RES, BUF_H1, bn0_g, bn0_b, bn0_m, bn0_v);

    // layer 1: two GEMMs from h1, aggregate with identity residual
    k_gemm<<<gg, 256>>>(nullptr, BUF_H1, off1l, nullptr, BUF_YL, NN, HID);
    k_gemm<<<gg, 256>>>(nullptr, BUF_H1, off1r, bl1,     BUF_YR, NN, HID);
    k_agg<<<agg_blocks, 256>>>(BUF_H1, BUF_H2, bn1_g, bn1_b, bn1_m, bn1_v);

    // layer 2: tiny per-node output transform, then 2-wide aggregation
    k_out<<<agg_blocks, 256>>>(Wl2, Wr2, bl2);
    k_final<<<(NN + 255) / 256, 256>>>((float*)d_out);
}

// round 5
// speedup vs baseline: 1.6844x; 1.6844x over previous
#include <cuda_runtime.h>
#include <cuda_bf16.h>

#define NN 50000
#define NE 800000
#define IN_DIM 166
#define HID 128
#define BN_EPS 1e-5f
#define SCAN_NB 196   // ceil(NN/256)

// ---------------- scratch (device globals; float4-typed => 16B-aligned) ----------------
__device__ int    g_is64;           // edge_index dtype flag (1 = int64, 0 = int32)
__device__ int    g_deg[NN];
__device__ int    g_rowptr[NN + 1];
__device__ int    g_cursor[NN];
__device__ int    g_bsum[SCAN_NB];
__device__ int    g_col[NE];
__device__ float4 g_yl[NN * 32];    // [NN,128] fp32
__device__ float4 g_yr[NN * 32];
__device__ float4 g_res[NN * 32];
__device__ float4 g_h1[NN * 32];
__device__ float4 g_h2[NN * 32];
__device__ float4 g_y2[NN];         // [NN,4]
__device__ float4 g_wt[(3 * IN_DIM * HID + 2 * HID * HID) / 4]; // transposed weights

// buffer selectors (device-side pointer resolution)
#define BUF_YL  0
#define BUF_YR  1
#define BUF_RES 2
#define BUF_H1  3
#define BUF_H2  4
__device__ __forceinline__ float4* buf_ptr(int s) {
    switch (s) {
        case BUF_YL:  return g_yl;
        case BUF_YR:  return g_yr;
        case BUF_RES: return g_res;
        case BUF_H1:  return g_h1;
        default:      return g_h2;
    }
}

__device__ __forceinline__ int clamp_node(int v) {
    return v < 0 ? 0 : (v >= NN ? NN - 1 : v);
}

__device__ __forceinline__ int edge_val(const void* ei, int is64, int half, int i) {
    if (is64) {
        long long v = ((const long long*)ei)[(size_t)half * NE + i];
        return clamp_node((int)v);
    } else {
        int v = ((const int*)ei)[(size_t)half * NE + i];
        return clamp_node(v);
    }
}

// ---------------- tf32 helpers ----------------
__device__ __forceinline__ unsigned f2tf32(float f) {
    unsigned r;
    asm("cvt.rna.tf32.f32 %0, %1;" : "=r"(r) : "f"(f));
    return r;
}
__device__ __forceinline__ void mma_tf32(float c[4], const unsigned a[4],
                                         unsigned b0, unsigned b1) {
    asm("mma.sync.aligned.m16n8k8.row.col.f32.tf32.tf32.f32 "
        "{%0,%1,%2,%3}, {%4,%5,%6,%7}, {%8,%9}, {%0,%1,%2,%3};"
        : "+f"(c[0]), "+f"(c[1]), "+f"(c[2]), "+f"(c[3])
        : "r"(a[0]), "r"(a[1]), "r"(a[2]), "r"(a[3]), "r"(b0), "r"(b1));
}

// ---------------- dtype detection ----------------
__global__ void k_detect(const int* __restrict__ w) {
    if (threadIdx.x == 0 && blockIdx.x == 0) {
        int all_zero = 1;
        for (int t = 0; t < 32; t++) {
            if (w[2 * t + 1] != 0) { all_zero = 0; break; }
        }
        g_is64 = all_zero;
    }
}

// ---------------- CSR build ----------------
__global__ void k_zero_int(int n) {
    int i = blockIdx.x * blockDim.x + threadIdx.x;
    if (i < n) g_deg[i] = 0;
}

__global__ void k_hist(const void* __restrict__ ei) {
    int i = blockIdx.x * blockDim.x + threadIdx.x;
    if (i < NE) {
        int dst = edge_val(ei, g_is64, 1, i);
        atomicAdd(&g_deg[dst], 1);
    }
}

// phase 1: per-block exclusive scan (local), store block totals
__global__ void k_scan1() {
    __shared__ int sm[256];
    int b = blockIdx.x, t = threadIdx.x;
    int i = b * 256 + t;
    int v = (i < NN) ? g_deg[i] : 0;
    sm[t] = v;
    __syncthreads();
    for (int off = 1; off < 256; off <<= 1) {
        int u = (t >= off) ? sm[t - off] : 0;
        __syncthreads();
        sm[t] += u;
        __syncthreads();
    }
    if (i < NN) g_rowptr[i] = sm[t] - v;   // local exclusive
    if (t == 255) g_bsum[b] = sm[255];
}

// phase 2: exclusive scan of the 196 block sums (one block)
__global__ void k_scan2() {
    __shared__ int sm[256];
    int t = threadIdx.x;
    int v = (t < SCAN_NB) ? g_bsum[t] : 0;
    sm[t] = v;
    __syncthreads();
    for (int off = 1; off < 256; off <<= 1) {
        int u = (t >= off) ? sm[t - off] : 0;
        __syncthreads();
        sm[t] += u;
        __syncthreads();
    }
    if (t < SCAN_NB) g_bsum[t] = sm[t] - v;
}

// phase 3: add block offsets, init cursor, set sentinel
__global__ void k_scan3() {
    int i = blockIdx.x * blockDim.x + threadIdx.x;
    if (i < NN) {
        int r = g_rowptr[i] + g_bsum[i >> 8];
        g_rowptr[i] = r;
        g_cursor[i] = r;
    }
    if (i == 0) g_rowptr[NN] = NE;  // clamped dsts => every edge lands in range
}

__global__ void k_scatter(const void* __restrict__ ei) {
    int i = blockIdx.x * blockDim.x + threadIdx.x;
    if (i < NE) {
        int is64 = g_is64;
        int src = edge_val(ei, is64, 0, i);
        int dst = edge_val(ei, is64, 1, i);
        int pos = atomicAdd(&g_cursor[dst], 1);
        if (pos >= 0 && pos < NE) g_col[pos] = src;
    }
}

// ---------------- weight transpose: W[N,K] row-major -> g_wt[off + k*N + n] ----------------
__global__ void k_transpose(const float* __restrict__ W, int woff, int Nr, int K) {
    float* wt = reinterpret_cast<float*>(g_wt);
    int i = blockIdx.x * blockDim.x + threadIdx.x;
    if (i < Nr * K) {
        int n = i / K, k = i % K;
        wt[woff + k * Nr + n] = W[i];
    }
}

// ---------------- tf32 tensor-core GEMM: C[M,128] = A[M,K] @ Wt[K,128] (+bias) ----------------
// 128x128 block tile, BK=16, 8 warps (4 row x 2 col), warp tile 32x64, mma m16n8k8.
#define AS_ST 20    // As[m][k] stride: banks 20g mod 32 distinct for g=0..7
#define BS_ST 136   // Bs[k][n] stride: banks 8k+g all distinct

__global__ __launch_bounds__(256) void k_gemm_tc(
    const float* __restrict__ Ax,   // used when a_sel < 0
    int a_sel,
    int woff,
    const float* __restrict__ bias, // may be null
    int out_sel,
    int M, int K)
{
    __shared__ unsigned As[128 * AS_ST];
    __shared__ unsigned Bs[16 * BS_ST];

    const float* A = (a_sel < 0) ? Ax : reinterpret_cast<const float*>(buf_ptr(a_sel));
    float* C = reinterpret_cast<float*>(buf_ptr(out_sel));
    const float* Wt = reinterpret_cast<const float*>(g_wt) + woff;

    int tid = threadIdx.x;
    int lane = tid & 31, wid = tid >> 5;
    int wr = wid & 3, wc = wid >> 2;     // warp row 0..3, warp col 0..1
    int m0 = blockIdx.x * 128;
    int gq = lane >> 2, tq = lane & 3;   // groupID, threadID-in-group

    float acc[2][8][4];
#pragma unroll
    for (int mt = 0; mt < 2; mt++)
#pragma unroll
        for (int ct = 0; ct < 8; ct++)
#pragma unroll
            for (int j = 0; j < 4; j++) acc[mt][ct][j] = 0.f;

    int KT = (K + 15) >> 4;
    for (int kt = 0; kt < KT; kt++) {
        int k0 = kt * 16;
        // A tile 128x16 -> As[m][k]
#pragma unroll
        for (int i = 0; i < 8; i++) {
            int l = tid + i * 256;
            int k = l & 15, m = l >> 4;
            float v = 0.f;
            int gm = m0 + m, gk = k0 + k;
            if (gm < M && gk < K) v = A[(size_t)gm * K + gk];
            As[m * AS_ST + k] = f2tf32(v);
        }
        // B tile 16x128 -> Bs[k][n]
#pragma unroll
        for (int i = 0; i < 8; i++) {
            int l = tid + i * 256;
            int n = l & 127, k = l >> 7;
            float v = 0.f;
            int gk = k0 + k;
            if (gk < K) v = Wt[(size_t)gk * 128 + n];
            Bs[k * BS_ST + n] = f2tf32(v);
        }
        __syncthreads();
#pragma unroll
        for (int ks = 0; ks < 16; ks += 8) {
            unsigned af[2][4];
#pragma unroll
            for (int mt = 0; mt < 2; mt++) {
                int mb = wr * 32 + mt * 16;
                af[mt][0] = As[(mb + gq) * AS_ST + ks + tq];
                af[mt][1] = As[(mb + gq + 8) * AS_ST + ks + tq];
                af[mt][2] = As[(mb + gq) * AS_ST + ks + tq + 4];
                af[mt][3] = As[(mb + gq + 8) * AS_ST + ks + tq + 4];
            }
#pragma unroll
            for (int ct = 0; ct < 8; ct++) {
                int nb = wc * 64 + ct * 8;
                unsigned b0 = Bs[(ks + tq) * BS_ST + nb + gq];
                unsigned b1 = Bs[(ks + tq + 4) * BS_ST + nb + gq];
                mma_tf32(acc[0][ct], af[0], b0, b1);
                mma_tf32(acc[1][ct], af[1], b0, b1);
            }
        }
        __syncthreads();
    }

    // epilogue: c0,c1 -> (row, t*2 / t*2+1); c2,c3 -> row+8
#pragma unroll
    for (int mt = 0; mt < 2; mt++) {
        int r0 = m0 + wr * 32 + mt * 16 + gq;
#pragma unroll
        for (int ct = 0; ct < 8; ct++) {
            int n = wc * 64 + ct * 8 + tq * 2;
            float b0v = 0.f, b1v = 0.f;
            if (bias != nullptr) { b0v = bias[n]; b1v = bias[n + 1]; }
            if (r0 < M) {
                float2 o = make_float2(acc[mt][ct][0] + b0v, acc[mt][ct][1] + b1v);
                *(float2*)&C[(size_t)r0 * 128 + n] = o;
            }
            if (r0 + 8 < M) {
                float2 o = make_float2(acc[mt][ct][2] + b0v, acc[mt][ct][3] + b1v);
                *(float2*)&C[(size_t)(r0 + 8) * 128 + n] = o;
            }
        }
    }
}

// ---------------- aggregation + BN + ReLU + residual (warp per node) ----------------
__global__ __launch_bounds__(256) void k_agg(
    int res_sel, int out_sel,
    const float* __restrict__ bn_g, const float* __restrict__ bn_b,
    const float* __restrict__ bn_m, const float* __restrict__ bn_v)
{
    const float4* __restrict__ yl  = g_yl;
    const float4* __restrict__ yr  = g_yr;
    const float4* __restrict__ res = buf_ptr(res_sel);
    float4* __restrict__ out       = buf_ptr(out_sel);
    const int* __restrict__ col    = g_col;

    int w = (blockIdx.x * blockDim.x + threadIdx.x) >> 5;
    int lane = threadIdx.x & 31;
    if (w >= NN) return;
    int s0 = g_rowptr[w], s1 = g_rowptr[w + 1];

    float ax = 0.f, ay = 0.f, az = 0.f, aw = 0.f;
    int e = s0;
    for (; e + 1 < s1; e += 2) {
        int sA = clamp_node(col[e]);
        int sB = clamp_node(col[e + 1]);
        float4 vA = yl[sA * 32 + lane];
        float4 vB = yl[sB * 32 + lane];
        ax += vA.x; ay += vA.y; az += vA.z; aw += vA.w;
        ax += vB.x; ay += vB.y; az += vB.z; aw += vB.w;
    }
    if (e < s1) {
        int sA = clamp_node(col[e]);
        float4 vA = yl[sA * 32 + lane];
        ax += vA.x; ay += vA.y; az += vA.z; aw += vA.w;
    }

    int deg = s1 - s0;
    float inv = 1.f / (float)(deg > 1 ? deg : 1);
    float4 r = yr[w * 32 + lane];
    int f = lane * 4;
    float gx = bn_g[f], gy = bn_g[f + 1], gz = bn_g[f + 2], gw = bn_g[f + 3];
    float bx = bn_b[f], by = bn_b[f + 1], bz = bn_b[f + 2], bw = bn_b[f + 3];
    float mx = bn_m[f], my = bn_m[f + 1], mz = bn_m[f + 2], mw = bn_m[f + 3];
    float qx = bn_v[f], qy = bn_v[f + 1], qz = bn_v[f + 2], qw = bn_v[f + 3];
    float4 rr = res[w * 32 + lane];

    float sx = gx * rsqrtf(qx + BN_EPS);
    float sy = gy * rsqrtf(qy + BN_EPS);
    float sz = gz * rsqrtf(qz + BN_EPS);
    float sw = gw * rsqrtf(qw + BN_EPS);

    float vx = (ax * inv + r.x - mx) * sx + bx;
    float vy = (ay * inv + r.y - my) * sy + by;
    float vz = (az * inv + r.z - mz) * sz + bz;
    float vw = (aw * inv + r.w - mw) * sw + bw;
    vx = fmaxf(vx, 0.f) + rr.x;
    vy = fmaxf(vy, 0.f) + rr.y;
    vz = fmaxf(vz, 0.f) + rr.z;
    vw = fmaxf(vw, 0.f) + rr.w;

    out[w * 32 + lane] = make_float4(vx, vy, vz, vw);
}

// ---------------- layer-2 small GEMM ----------------
__global__ __launch_bounds__(256) void k_out(
    const float* __restrict__ Wl2, const float* __restrict__ Wr2,
    const float* __restrict__ bl2)
{
    const float4* __restrict__ h = g_h2;
    int w = (blockIdx.x * blockDim.x + threadIdx.x) >> 5;
    int lane = threadIdx.x & 31;
    if (w >= NN) return;
    float4 hv = h[w * 32 + lane];
    int f = lane * 4;
    float a0 = Wl2[f], a1 = Wl2[f + 1], a2 = Wl2[f + 2], a3 = Wl2[f + 3];
    float b0 = Wl2[128 + f], b1 = Wl2[128 + f + 1], b2 = Wl2[128 + f + 2], b3 = Wl2[128 + f + 3];
    float c0 = Wr2[f], c1 = Wr2[f + 1], c2 = Wr2[f + 2], c3 = Wr2[f + 3];
    float e0 = Wr2[128 + f], e1 = Wr2[128 + f + 1], e2 = Wr2[128 + f + 2], e3 = Wr2[128 + f + 3];
    float d0 = hv.x * a0 + hv.y * a1 + hv.z * a2 + hv.w * a3;
    float d1 = hv.x * b0 + hv.y * b1 + hv.z * b2 + hv.w * b3;
    float d2 = hv.x * c0 + hv.y * c1 + hv.z * c2 + hv.w * c3;
    float d3 = hv.x * e0 + hv.y * e1 + hv.z * e2 + hv.w * e3;
#pragma unroll
    for (int off = 16; off; off >>= 1) {
        d0 += __shfl_xor_sync(0xffffffffu, d0, off);
        d1 += __shfl_xor_sync(0xffffffffu, d1, off);
        d2 += __shfl_xor_sync(0xffffffffu, d2, off);
        d3 += __shfl_xor_sync(0xffffffffu, d3, off);
    }
    if (lane == 0) {
        g_y2[w] = make_float4(d0, d1, d2 + bl2[0], d3 + bl2[1]);
    }
}

// ---------------- final: aggregate 2-wide logits + root term ----------------
__global__ void k_final(float* __restrict__ out)
{
    int i = blockIdx.x * blockDim.x + threadIdx.x;
    if (i >= NN) return;
    int s0 = g_rowptr[i], s1 = g_rowptr[i + 1];
    float a0 = 0.f, a1 = 0.f;
    for (int e = s0; e < s1; e++) {
        int s = clamp_node(g_col[e]);
        float4 v = g_y2[s];
        a0 += v.x;
        a1 += v.y;
    }
    int deg = s1 - s0;
    float inv = 1.f / (float)(deg > 1 ? deg : 1);
    float4 self = g_y2[i];
    out[2 * i + 0] = a0 * inv + self.z;
    out[2 * i + 1] = a1 * inv + self.w;
}

// ---------------- launch ----------------
extern "C" void kernel_launch(void* const* d_in, const int* in_sizes, int n_in,
                              void* d_out, int out_size)
{
    const float* x     = (const float*)d_in[0];
    const void*  ei    = (const void*)d_in[1];
    const float* Wl0   = (const float*)d_in[2];
    const float* bl0   = (const float*)d_in[3];
    const float* Wr0   = (const float*)d_in[4];
    const float* Wl1   = (const float*)d_in[5];
    const float* bl1   = (const float*)d_in[6];
    const float* Wr1   = (const float*)d_in[7];
    const float* Wl2   = (const float*)d_in[8];
    const float* bl2   = (const float*)d_in[9];
    const float* Wr2   = (const float*)d_in[10];
    const float* Wres0 = (const float*)d_in[11];
    const float* bn0_g = (const float*)d_in[12];
    const float* bn0_b = (const float*)d_in[13];
    const float* bn0_m = (const float*)d_in[14];
    const float* bn0_v = (const float*)d_in[15];
    const float* bn1_g = (const float*)d_in[16];
    const float* bn1_b = (const float*)d_in[17];
    const float* bn1_m = (const float*)d_in[18];
    const float* bn1_v = (const float*)d_in[19];

    const int off0l = 0;
    const int off0r = IN_DIM * HID;
    const int off0s = 2 * IN_DIM * HID;
    const int off1l = 3 * IN_DIM * HID;
    const int off1r = 3 * IN_DIM * HID + HID * HID;

    // dtype detection + CSR build (parallel scan)
    k_detect<<<1, 32>>>((const int*)ei);
    k_zero_int<<<(NN + 255) / 256, 256>>>(NN);
    k_hist<<<(NE + 255) / 256, 256>>>(ei);
    k_scan1<<<SCAN_NB, 256>>>();
    k_scan2<<<1, 256>>>();
    k_scan3<<<SCAN_NB, 256>>>();
    k_scatter<<<(NE + 255) / 256, 256>>>(ei);

    // weight transposes
    int tw0 = HID * IN_DIM, tw1 = HID * HID;
    k_transpose<<<(tw0 + 255) / 256, 256>>>(Wl0,   off0l, HID, IN_DIM);
    k_transpose<<<(tw0 + 255) / 256, 256>>>(Wr0,   off0r, HID, IN_DIM);
    k_transpose<<<(tw0 + 255) / 256, 256>>>(Wres0, off0s, HID, IN_DIM);
    k_transpose<<<(tw1 + 255) / 256, 256>>>(Wl1,   off1l, HID, HID);
    k_transpose<<<(tw1 + 255) / 256, 256>>>(Wr1,   off1r, HID, HID);

    dim3 gg((NN + 127) / 128, 1);
    int agg_blocks = (NN * 32 + 255) / 256;

    // layer 0: three GEMMs from x, then aggregate + BN + ReLU + residual
    k_gemm_tc<<<gg, 256>>>(x, -1, off0l, nullptr, BUF_YL,  NN, IN_DIM);
    k_gemm_tc<<<gg, 256>>>(x, -1, off0r, bl0,     BUF_YR,  NN, IN_DIM);
    k_gemm_tc<<<gg, 256>>>(x, -1, off0s, nullptr, BUF_RES, NN, IN_DIM);
    k_agg<<<agg_blocks, 256>>>(BUF_RES, BUF_H1, bn0_g, bn0_b, bn0_m, bn0_v);

    // layer 1: two GEMMs from h1, aggregate with identity residual
    k_gemm_tc<<<gg, 256>>>(nullptr, BUF_H1, off1l, nullptr, BUF_YL, NN, HID);
    k_gemm_tc<<<gg, 256>>>(nullptr, BUF_H1, off1r, bl1,     BUF_YR, NN, HID);
    k_agg<<<agg_blocks, 256>>>(BUF_H1, BUF_H2, bn1_g, bn1_b, bn1_m, bn1_v);

    // layer 2: tiny per-node output transform, then 2-wide aggregation
    k_out<<<agg_blocks, 256>>>(Wl2, Wr2, bl2);
    k_final<<<(NN + 255) / 256, 256>>>((float*)d_out);
}

// round 6
// speedup vs baseline: 1.8548x; 1.1012x over previous
#include <cuda_runtime.h>
#include <cuda_bf16.h>

#define NN 50000
#define NE 800000
#define IN_DIM 166
#define HID 128
#define BN_EPS 1e-5f
#define SCAN_NB 196   // ceil(NN/256)

// ---------------- scratch (device globals; float4-typed => 16B-aligned) ----------------
__device__ int    g_is64;
__device__ int    g_deg[NN];
__device__ int    g_rowptr[NN + 1];
__device__ int    g_cursor[NN];
__device__ int    g_bsum[SCAN_NB];
__device__ int    g_src[NE];
__device__ int    g_dst[NE];
__device__ int    g_col[NE];
__device__ float4 g_yl[NN * 32];    // [NN,128] fp32
__device__ float4 g_yr[NN * 32];
__device__ float4 g_res[NN * 32];
__device__ float4 g_h1[NN * 32];
__device__ float4 g_h2[NN * 32];
__device__ float4 g_y2[NN];         // [NN,4]
__device__ float4 g_wt[(3 * IN_DIM * HID + 2 * HID * HID) / 4];

// buffer selectors
#define BUF_YL  0
#define BUF_YR  1
#define BUF_RES 2
#define BUF_H1  3
#define BUF_H2  4
__device__ __forceinline__ float4* buf_ptr(int s) {
    switch (s) {
        case BUF_YL:  return g_yl;
        case BUF_YR:  return g_yr;
        case BUF_RES: return g_res;
        case BUF_H1:  return g_h1;
        default:      return g_h2;
    }
}

__device__ __forceinline__ int clamp_node(int v) {
    return v < 0 ? 0 : (v >= NN ? NN - 1 : v);
}

// ---------------- tf32 helpers ----------------
__device__ __forceinline__ unsigned f2tf32(float f) {
    unsigned r;
    asm("cvt.rna.tf32.f32 %0, %1;" : "=r"(r) : "f"(f));
    return r;
}
__device__ __forceinline__ void mma_tf32(float c[4], const unsigned a[4],
                                         unsigned b0, unsigned b1) {
    asm("mma.sync.aligned.m16n8k8.row.col.f32.tf32.tf32.f32 "
        "{%0,%1,%2,%3}, {%4,%5,%6,%7}, {%8,%9}, {%0,%1,%2,%3};"
        : "+f"(c[0]), "+f"(c[1]), "+f"(c[2]), "+f"(c[3])
        : "r"(a[0]), "r"(a[1]), "r"(a[2]), "r"(a[3]), "r"(b0), "r"(b1));
}

// ---------------- dtype detection ----------------
__global__ void k_detect(const int* __restrict__ w) {
    if (threadIdx.x == 0 && blockIdx.x == 0) {
        int all_zero = 1;
        for (int t = 0; t < 32; t++) {
            if (w[2 * t + 1] != 0) { all_zero = 0; break; }
        }
        g_is64 = all_zero;
    }
}

// ---------------- edge conversion (int64|int32 -> int32 src/dst) + deg zero ----------------
__global__ void e_cvt(const void* __restrict__ ei) {
    int i = blockIdx.x * blockDim.x + threadIdx.x;
    if (i < NN) g_deg[i] = 0;
    if (i < NE) {
        int is64 = g_is64;
        int s, d;
        if (is64) {
            s = (int)((const long long*)ei)[i];
            d = (int)((const long long*)ei)[NE + i];
        } else {
            s = ((const int*)ei)[i];
            d = ((const int*)ei)[NE + i];
        }
        g_src[i] = clamp_node(s);
        g_dst[i] = clamp_node(d);
    }
}

// ---------------- CSR build ----------------
__global__ void k_hist() {
    int i = blockIdx.x * blockDim.x + threadIdx.x;
    if (i < NE) atomicAdd(&g_deg[g_dst[i]], 1);
}

__global__ void k_scan1() {
    __shared__ int sm[256];
    int b = blockIdx.x, t = threadIdx.x;
    int i = b * 256 + t;
    int v = (i < NN) ? g_deg[i] : 0;
    sm[t] = v;
    __syncthreads();
    for (int off = 1; off < 256; off <<= 1) {
        int u = (t >= off) ? sm[t - off] : 0;
        __syncthreads();
        sm[t] += u;
        __syncthreads();
    }
    if (i < NN) g_rowptr[i] = sm[t] - v;
    if (t == 255) g_bsum[b] = sm[255];
}

__global__ void k_scan2() {
    __shared__ int sm[256];
    int t = threadIdx.x;
    int v = (t < SCAN_NB) ? g_bsum[t] : 0;
    sm[t] = v;
    __syncthreads();
    for (int off = 1; off < 256; off <<= 1) {
        int u = (t >= off) ? sm[t - off] : 0;
        __syncthreads();
        sm[t] += u;
        __syncthreads();
    }
    if (t < SCAN_NB) g_bsum[t] = sm[t] - v;
}

__global__ void k_scan3() {
    int i = blockIdx.x * blockDim.x + threadIdx.x;
    if (i < NN) {
        int r = g_rowptr[i] + g_bsum[i >> 8];
        g_rowptr[i] = r;
        g_cursor[i] = r;
    }
    if (i == 0) g_rowptr[NN] = NE;
}

__global__ void k_scatter() {
    int i = blockIdx.x * blockDim.x + threadIdx.x;
    if (i < NE) {
        int pos = atomicAdd(&g_cursor[g_dst[i]], 1);
        if (pos >= 0 && pos < NE) g_col[pos] = g_src[i];
    }
}

// ---------------- weight transpose ----------------
__global__ void k_transpose(const float* __restrict__ W, int woff, int Nr, int K) {
    float* wt = reinterpret_cast<float*>(g_wt);
    int i = blockIdx.x * blockDim.x + threadIdx.x;
    if (i < Nr * K) {
        int n = i / K, k = i % K;
        wt[woff + k * Nr + n] = W[i];
    }
}

// ---------------- tf32 tensor-core GEMM (multi-weight via blockIdx.y) ----------------
#define AS_ST 20
#define BS_ST 136

__global__ __launch_bounds__(256) void k_gemm_tc(
    const float* __restrict__ Ax,   // used when a_sel < 0
    int a_sel,
    int woff0, int woff1, int woff2,   // weight offsets per blockIdx.y
    int osel0, int osel1, int osel2,   // output selectors per blockIdx.y
    const float* __restrict__ bias,    // applied only for blockIdx.y == 1
    int M, int K)
{
    __shared__ unsigned As[128 * AS_ST];
    __shared__ unsigned Bs[16 * BS_ST];

    int yb = blockIdx.y;
    int woff = (yb == 0) ? woff0 : (yb == 1) ? woff1 : woff2;
    int osel = (yb == 0) ? osel0 : (yb == 1) ? osel1 : osel2;
    const float* bp = (yb == 1) ? bias : nullptr;

    const float* A = (a_sel < 0) ? Ax : reinterpret_cast<const float*>(buf_ptr(a_sel));
    float* C = reinterpret_cast<float*>(buf_ptr(osel));
    const float* Wt = reinterpret_cast<const float*>(g_wt) + woff;

    int tid = threadIdx.x;
    int lane = tid & 31, wid = tid >> 5;
    int wr = wid & 3, wc = wid >> 2;
    int m0 = blockIdx.x * 128;
    int gq = lane >> 2, tq = lane & 3;

    float acc[2][8][4];
#pragma unroll
    for (int mt = 0; mt < 2; mt++)
#pragma unroll
        for (int ct = 0; ct < 8; ct++)
#pragma unroll
            for (int j = 0; j < 4; j++) acc[mt][ct][j] = 0.f;

    int KT = (K + 15) >> 4;
    for (int kt = 0; kt < KT; kt++) {
        int k0 = kt * 16;
#pragma unroll
        for (int i = 0; i < 8; i++) {
            int l = tid + i * 256;
            int k = l & 15, m = l >> 4;
            float v = 0.f;
            int gm = m0 + m, gk = k0 + k;
            if (gm < M && gk < K) v = A[(size_t)gm * K + gk];
            As[m * AS_ST + k] = f2tf32(v);
        }
#pragma unroll
        for (int i = 0; i < 8; i++) {
            int l = tid + i * 256;
            int n = l & 127, k = l >> 7;
            float v = 0.f;
            int gk = k0 + k;
            if (gk < K) v = Wt[(size_t)gk * 128 + n];
            Bs[k * BS_ST + n] = f2tf32(v);
        }
        __syncthreads();
#pragma unroll
        for (int ks = 0; ks < 16; ks += 8) {
            unsigned af[2][4];
#pragma unroll
            for (int mt = 0; mt < 2; mt++) {
                int mb = wr * 32 + mt * 16;
                af[mt][0] = As[(mb + gq) * AS_ST + ks + tq];
                af[mt][1] = As[(mb + gq + 8) * AS_ST + ks + tq];
                af[mt][2] = As[(mb + gq) * AS_ST + ks + tq + 4];
                af[mt][3] = As[(mb + gq + 8) * AS_ST + ks + tq + 4];
            }
#pragma unroll
            for (int ct = 0; ct < 8; ct++) {
                int nb = wc * 64 + ct * 8;
                unsigned b0 = Bs[(ks + tq) * BS_ST + nb + gq];
                unsigned b1 = Bs[(ks + tq + 4) * BS_ST + nb + gq];
                mma_tf32(acc[0][ct], af[0], b0, b1);
                mma_tf32(acc[1][ct], af[1], b0, b1);
            }
        }
        __syncthreads();
    }

#pragma unroll
    for (int mt = 0; mt < 2; mt++) {
        int r0 = m0 + wr * 32 + mt * 16 + gq;
#pragma unroll
        for (int ct = 0; ct < 8; ct++) {
            int n = wc * 64 + ct * 8 + tq * 2;
            float b0v = 0.f, b1v = 0.f;
            if (bp != nullptr) { b0v = bp[n]; b1v = bp[n + 1]; }
            if (r0 < M) {
                float2 o = make_float2(acc[mt][ct][0] + b0v, acc[mt][ct][1] + b1v);
                *(float2*)&C[(size_t)r0 * 128 + n] = o;
            }
            if (r0 + 8 < M) {
                float2 o = make_float2(acc[mt][ct][2] + b0v, acc[mt][ct][3] + b1v);
                *(float2*)&C[(size_t)(r0 + 8) * 128 + n] = o;
            }
        }
    }
}

// ---------------- aggregation + BN + ReLU + residual (+ optional fused output layer) ----
__global__ __launch_bounds__(256) void k_agg(
    int res_sel, int out_sel,
    const float* __restrict__ bn_g, const float* __restrict__ bn_b,
    const float* __restrict__ bn_m, const float* __restrict__ bn_v,
    int do_out,
    const float* __restrict__ Wl2, const float* __restrict__ Wr2,
    const float* __restrict__ bl2)
{
    const float4* __restrict__ yl  = g_yl;
    const float4* __restrict__ yr  = g_yr;
    const float4* __restrict__ res = buf_ptr(res_sel);
    float4* __restrict__ out       = buf_ptr(out_sel);
    const int* __restrict__ col    = g_col;

    int w = (blockIdx.x * blockDim.x + threadIdx.x) >> 5;
    int lane = threadIdx.x & 31;
    if (w >= NN) return;
    int s0 = g_rowptr[w], s1 = g_rowptr[w + 1];

    float ax = 0.f, ay = 0.f, az = 0.f, aw = 0.f;
    int e = s0;
    // 4-way unrolled gather: 4 independent 512B row loads in flight
    for (; e + 3 < s1; e += 4) {
        int sA = clamp_node(col[e]);
        int sB = clamp_node(col[e + 1]);
        int sC = clamp_node(col[e + 2]);
        int sD = clamp_node(col[e + 3]);
        float4 vA = yl[sA * 32 + lane];
        float4 vB = yl[sB * 32 + lane];
        float4 vC = yl[sC * 32 + lane];
        float4 vD = yl[sD * 32 + lane];
        ax += vA.x + vB.x + vC.x + vD.x;
        ay += vA.y + vB.y + vC.y + vD.y;
        az += vA.z + vB.z + vC.z + vD.z;
        aw += vA.w + vB.w + vC.w + vD.w;
    }
    for (; e < s1; e++) {
        int sA = clamp_node(col[e]);
        float4 vA = yl[sA * 32 + lane];
        ax += vA.x; ay += vA.y; az += vA.z; aw += vA.w;
    }

    int deg = s1 - s0;
    float inv = 1.f / (float)(deg > 1 ? deg : 1);
    float4 r = yr[w * 32 + lane];
    int f = lane * 4;
    float gx = bn_g[f], gy = bn_g[f + 1], gz = bn_g[f + 2], gw = bn_g[f + 3];
    float bx = bn_b[f], by = bn_b[f + 1], bz = bn_b[f + 2], bw = bn_b[f + 3];
    float mx = bn_m[f], my = bn_m[f + 1], mz = bn_m[f + 2], mw = bn_m[f + 3];
    float qx = bn_v[f], qy = bn_v[f + 1], qz = bn_v[f + 2], qw = bn_v[f + 3];
    float4 rr = res[w * 32 + lane];

    float sx = gx * rsqrtf(qx + BN_EPS);
    float sy = gy * rsqrtf(qy + BN_EPS);
    float sz = gz * rsqrtf(qz + BN_EPS);
    float sw = gw * rsqrtf(qw + BN_EPS);

    float vx = (ax * inv + r.x - mx) * sx + bx;
    float vy = (ay * inv + r.y - my) * sy + by;
    float vz = (az * inv + r.z - mz) * sz + bz;
    float vw = (aw * inv + r.w - mw) * sw + bw;
    vx = fmaxf(vx, 0.f) + rr.x;
    vy = fmaxf(vy, 0.f) + rr.y;
    vz = fmaxf(vz, 0.f) + rr.z;
    vw = fmaxf(vw, 0.f) + rr.w;

    out[w * 32 + lane] = make_float4(vx, vy, vz, vw);

    if (do_out) {
        // fused output-layer dots: y2[w] = [Wl2 row0/1 . h, Wr2 row0/1 . h]
        float a0 = Wl2[f], a1 = Wl2[f + 1], a2 = Wl2[f + 2], a3 = Wl2[f + 3];
        float b0 = Wl2[128 + f], b1 = Wl2[128 + f + 1], b2 = Wl2[128 + f + 2], b3 = Wl2[128 + f + 3];
        float c0 = Wr2[f], c1 = Wr2[f + 1], c2 = Wr2[f + 2], c3 = Wr2[f + 3];
        float e0 = Wr2[128 + f], e1 = Wr2[128 + f + 1], e2 = Wr2[128 + f + 2], e3 = Wr2[128 + f + 3];
        float d0 = vx * a0 + vy * a1 + vz * a2 + vw * a3;
        float d1 = vx * b0 + vy * b1 + vz * b2 + vw * b3;
        float d2 = vx * c0 + vy * c1 + vz * c2 + vw * c3;
        float d3 = vx * e0 + vy * e1 + vz * e2 + vw * e3;
#pragma unroll
        for (int off = 16; off; off >>= 1) {
            d0 += __shfl_xor_sync(0xffffffffu, d0, off);
            d1 += __shfl_xor_sync(0xffffffffu, d1, off);
            d2 += __shfl_xor_sync(0xffffffffu, d2, off);
            d3 += __shfl_xor_sync(0xffffffffu, d3, off);
        }
        if (lane == 0) {
            g_y2[w] = make_float4(d0, d1, d2 + bl2[0], d3 + bl2[1]);
        }
    }
}

// ---------------- final: aggregate 2-wide logits + root term ----------------
__global__ void k_final(float* __restrict__ out)
{
    int i = blockIdx.x * blockDim.x + threadIdx.x;
    if (i >= NN) return;
    int s0 = g_rowptr[i], s1 = g_rowptr[i + 1];
    float a0 = 0.f, a1 = 0.f;
    int e = s0;
    for (; e + 3 < s1; e += 4) {
        float4 v0 = g_y2[clamp_node(g_col[e])];
        float4 v1 = g_y2[clamp_node(g_col[e + 1])];
        float4 v2 = g_y2[clamp_node(g_col[e + 2])];
        float4 v3 = g_y2[clamp_node(g_col[e + 3])];
        a0 += v0.x + v1.x + v2.x + v3.x;
        a1 += v0.y + v1.y + v2.y + v3.y;
    }
    for (; e < s1; e++) {
        float4 v = g_y2[clamp_node(g_col[e])];
        a0 += v.x;
        a1 += v.y;
    }
    int deg = s1 - s0;
    float inv = 1.f / (float)(deg > 1 ? deg : 1);
    float4 self = g_y2[i];
    out[2 * i + 0] = a0 * inv + self.z;
    out[2 * i + 1] = a1 * inv + self.w;
}

// ---------------- launch ----------------
extern "C" void kernel_launch(void* const* d_in, const int* in_sizes, int n_in,
                              void* d_out, int out_size)
{
    const float* x     = (const float*)d_in[0];
    const void*  ei    = (const void*)d_in[1];
    const float* Wl0   = (const float*)d_in[2];
    const float* bl0   = (const float*)d_in[3];
    const float* Wr0   = (const float*)d_in[4];
    const float* Wl1   = (const float*)d_in[5];
    const float* bl1   = (const float*)d_in[6];
    const float* Wr1   = (const float*)d_in[7];
    const float* Wl2   = (const float*)d_in[8];
    const float* bl2   = (const float*)d_in[9];
    const float* Wr2   = (const float*)d_in[10];
    const float* Wres0 = (const float*)d_in[11];
    const float* bn0_g = (const float*)d_in[12];
    const float* bn0_b = (const float*)d_in[13];
    const float* bn0_m = (const float*)d_in[14];
    const float* bn0_v = (const float*)d_in[15];
    const float* bn1_g = (const float*)d_in[16];
    const float* bn1_b = (const float*)d_in[17];
    const float* bn1_m = (const float*)d_in[18];
    const float* bn1_v = (const float*)d_in[19];

    const int off0l = 0;
    const int off0r = IN_DIM * HID;
    const int off0s = 2 * IN_DIM * HID;
    const int off1l = 3 * IN_DIM * HID;
    const int off1r = 3 * IN_DIM * HID + HID * HID;

    // dtype detect -> edge convert (+deg zero) -> CSR
    k_detect<<<1, 32>>>((const int*)ei);
    e_cvt<<<(NE + 255) / 256, 256>>>(ei);
    k_hist<<<(NE + 255) / 256, 256>>>();
    k_scan1<<<SCAN_NB, 256>>>();
    k_scan2<<<1, 256>>>();
    k_scan3<<<SCAN_NB, 256>>>();
    k_scatter<<<(NE + 255) / 256, 256>>>();

    // weight transposes
    int tw0 = HID * IN_DIM, tw1 = HID * HID;
    k_transpose<<<(tw0 + 255) / 256, 256>>>(Wl0,   off0l, HID, IN_DIM);
    k_transpose<<<(tw0 + 255) / 256, 256>>>(Wr0,   off0r, HID, IN_DIM);
    k_transpose<<<(tw0 + 255) / 256, 256>>>(Wres0, off0s, HID, IN_DIM);
    k_transpose<<<(tw1 + 255) / 256, 256>>>(Wl1,   off1l, HID, HID);
    k_transpose<<<(tw1 + 255) / 256, 256>>>(Wr1,   off1r, HID, HID);

    int gx = (NN + 127) / 128;
    int agg_blocks = (NN * 32 + 255) / 256;

    // layer 0: fused 3-weight GEMM launch, then aggregate
    k_gemm_tc<<<dim3(gx, 3), 256>>>(x, -1, off0l, off0r, off0s,
                                    BUF_YL, BUF_YR, BUF_RES, bl0, NN, IN_DIM);
    k_agg<<<agg_blocks, 256>>>(BUF_RES, BUF_H1, bn0_g, bn0_b, bn0_m, bn0_v,
                               0, nullptr, nullptr, nullptr);

    // layer 1: fused 2-weight GEMM launch, then aggregate + fused output layer
    k_gemm_tc<<<dim3(gx, 2), 256>>>(nullptr, BUF_H1, off1l, off1r, off1r,
                                    BUF_YL, BUF_YR, BUF_YR, bl1, NN, HID);
    k_agg<<<agg_blocks, 256>>>(BUF_H1, BUF_H2, bn1_g, bn1_b, bn1_m, bn1_v,
                               1, Wl2, Wr2, bl2);

    // final 2-wide aggregation
    k_final<<<(NN + 255) / 256, 256>>>((float*)d_out);
}

// round 7
// speedup vs baseline: 1.9521x; 1.0525x over previous
#include <cuda_runtime.h>
#include <cuda_bf16.h>

#define NN 50000
#define NE 800000
#define IN_DIM 166
#define HID 128
#define BN_EPS 1e-5f
#define SCAN_NB 196   // ceil(NN/256)

// ---------------- scratch (device globals; float4-typed => 16B-aligned) ----------------
__device__ int    g_is64;
__device__ int    g_deg[NN];
__device__ int    g_rowptr[NN + 1];
__device__ int    g_cursor[NN];
__device__ int    g_bsum[SCAN_NB];
__device__ int    g_src[NE];
__device__ int    g_dst[NE];
__device__ int    g_col[NE];
__device__ float4 g_yl[NN * 32];    // [NN,128] fp32
__device__ float4 g_yr[NN * 32];
__device__ float4 g_res[NN * 32];
__device__ float4 g_h1[NN * 32];
__device__ float4 g_h2[NN * 32];
__device__ float4 g_y2[NN];         // [NN,4]
__device__ float4 g_wt[(3 * IN_DIM * HID + 2 * HID * HID) / 4];

// buffer selectors
#define BUF_YL  0
#define BUF_YR  1
#define BUF_RES 2
#define BUF_H1  3
#define BUF_H2  4
__device__ __forceinline__ float4* buf_ptr(int s) {
    switch (s) {
        case BUF_YL:  return g_yl;
        case BUF_YR:  return g_yr;
        case BUF_RES: return g_res;
        case BUF_H1:  return g_h1;
        default:      return g_h2;
    }
}

__device__ __forceinline__ int clamp_node(int v) {
    return v < 0 ? 0 : (v >= NN ? NN - 1 : v);
}

// ---------------- tf32 helpers ----------------
__device__ __forceinline__ unsigned f2tf32(float f) {
    unsigned r;
    asm("cvt.rna.tf32.f32 %0, %1;" : "=r"(r) : "f"(f));
    return r;
}
__device__ __forceinline__ void mma_tf32(float c[4], const unsigned a[4],
                                         unsigned b0, unsigned b1) {
    asm("mma.sync.aligned.m16n8k8.row.col.f32.tf32.tf32.f32 "
        "{%0,%1,%2,%3}, {%4,%5,%6,%7}, {%8,%9}, {%0,%1,%2,%3};"
        : "+f"(c[0]), "+f"(c[1]), "+f"(c[2]), "+f"(c[3])
        : "r"(a[0]), "r"(a[1]), "r"(a[2]), "r"(a[3]), "r"(b0), "r"(b1));
}

// ---------------- dtype detection ----------------
__global__ void k_detect(const int* __restrict__ w) {
    if (threadIdx.x == 0 && blockIdx.x == 0) {
        int all_zero = 1;
        for (int t = 0; t < 32; t++) {
            if (w[2 * t + 1] != 0) { all_zero = 0; break; }
        }
        g_is64 = all_zero;
    }
}

__global__ void k_zero_deg() {
    int i = blockIdx.x * blockDim.x + threadIdx.x;
    if (i < NN) g_deg[i] = 0;
}

// ---------------- edge conversion + fused degree histogram ----------------
__global__ void e_cvt_hist(const void* __restrict__ ei) {
    int i = blockIdx.x * blockDim.x + threadIdx.x;
    if (i < NE) {
        int is64 = g_is64;
        int s, d;
        if (is64) {
            s = (int)((const long long*)ei)[i];
            d = (int)((const long long*)ei)[NE + i];
        } else {
            s = ((const int*)ei)[i];
            d = ((const int*)ei)[NE + i];
        }
        s = clamp_node(s);
        d = clamp_node(d);
        g_src[i] = s;
        g_dst[i] = d;
        atomicAdd(&g_deg[d], 1);
    }
}

// ---------------- CSR scan ----------------
__global__ void k_scan1() {
    __shared__ int sm[256];
    int b = blockIdx.x, t = threadIdx.x;
    int i = b * 256 + t;
    int v = (i < NN) ? g_deg[i] : 0;
    sm[t] = v;
    __syncthreads();
    for (int off = 1; off < 256; off <<= 1) {
        int u = (t >= off) ? sm[t - off] : 0;
        __syncthreads();
        sm[t] += u;
        __syncthreads();
    }
    if (i < NN) g_rowptr[i] = sm[t] - v;
    if (t == 255) g_bsum[b] = sm[255];
}

__global__ void k_scan2() {
    __shared__ int sm[256];
    int t = threadIdx.x;
    int v = (t < SCAN_NB) ? g_bsum[t] : 0;
    sm[t] = v;
    __syncthreads();
    for (int off = 1; off < 256; off <<= 1) {
        int u = (t >= off) ? sm[t - off] : 0;
        __syncthreads();
        sm[t] += u;
        __syncthreads();
    }
    if (t < SCAN_NB) g_bsum[t] = sm[t] - v;
}

__global__ void k_scan3() {
    int i = blockIdx.x * blockDim.x + threadIdx.x;
    if (i < NN) {
        int r = g_rowptr[i] + g_bsum[i >> 8];
        g_rowptr[i] = r;
        g_cursor[i] = r;
    }
    if (i == 0) g_rowptr[NN] = NE;
}

__global__ void k_scatter() {
    int i = blockIdx.x * blockDim.x + threadIdx.x;
    if (i < NE) {
        int pos = atomicAdd(&g_cursor[g_dst[i]], 1);
        if (pos >= 0 && pos < NE) g_col[pos] = g_src[i];
    }
}

// ---------------- weight transpose ----------------
__global__ void k_transpose(const float* __restrict__ W, int woff, int Nr, int K) {
    float* wt = reinterpret_cast<float*>(g_wt);
    int i = blockIdx.x * blockDim.x + threadIdx.x;
    if (i < Nr * K) {
        int n = i / K, k = i % K;
        wt[woff + k * Nr + n] = W[i];
    }
}

// ---------------- tf32 tensor-core GEMM (multi-weight via blockIdx.y) ----------------
#define AS_ST 20
#define BS_ST 136

__global__ __launch_bounds__(256) void k_gemm_tc(
    const float* __restrict__ Ax,
    int a_sel,
    int woff0, int woff1, int woff2,
    int osel0, int osel1, int osel2,
    const float* __restrict__ bias,    // applied only for blockIdx.y == 1
    int M, int K)
{
    __shared__ unsigned As[128 * AS_ST];
    __shared__ unsigned Bs[16 * BS_ST];

    int yb = blockIdx.y;
    int woff = (yb == 0) ? woff0 : (yb == 1) ? woff1 : woff2;
    int osel = (yb == 0) ? osel0 : (yb == 1) ? osel1 : osel2;
    const float* bp = (yb == 1) ? bias : nullptr;

    const float* A = (a_sel < 0) ? Ax : reinterpret_cast<const float*>(buf_ptr(a_sel));
    float* C = reinterpret_cast<float*>(buf_ptr(osel));
    const float* Wt = reinterpret_cast<const float*>(g_wt) + woff;

    int tid = threadIdx.x;
    int lane = tid & 31, wid = tid >> 5;
    int wr = wid & 3, wc = wid >> 2;
    int m0 = blockIdx.x * 128;
    int gq = lane >> 2, tq = lane & 3;

    float acc[2][8][4];
#pragma unroll
    for (int mt = 0; mt < 2; mt++)
#pragma unroll
        for (int ct = 0; ct < 8; ct++)
#pragma unroll
            for (int j = 0; j < 4; j++) acc[mt][ct][j] = 0.f;

    int KT = (K + 15) >> 4;
    for (int kt = 0; kt < KT; kt++) {
        int k0 = kt * 16;
#pragma unroll
        for (int i = 0; i < 8; i++) {
            int l = tid + i * 256;
            int k = l & 15, m = l >> 4;
            float v = 0.f;
            int gm = m0 + m, gk = k0 + k;
            if (gm < M && gk < K) v = A[(size_t)gm * K + gk];
            As[m * AS_ST + k] = f2tf32(v);
        }
#pragma unroll
        for (int i = 0; i < 8; i++) {
            int l = tid + i * 256;
            int n = l & 127, k = l >> 7;
            float v = 0.f;
            int gk = k0 + k;
            if (gk < K) v = Wt[(size_t)gk * 128 + n];
            Bs[k * BS_ST + n] = f2tf32(v);
        }
        __syncthreads();
#pragma unroll
        for (int ks = 0; ks < 16; ks += 8) {
            unsigned af[2][4];
#pragma unroll
            for (int mt = 0; mt < 2; mt++) {
                int mb = wr * 32 + mt * 16;
                af[mt][0] = As[(mb + gq) * AS_ST + ks + tq];
                af[mt][1] = As[(mb + gq + 8) * AS_ST + ks + tq];
                af[mt][2] = As[(mb + gq) * AS_ST + ks + tq + 4];
                af[mt][3] = As[(mb + gq + 8) * AS_ST + ks + tq + 4];
            }
#pragma unroll
            for (int ct = 0; ct < 8; ct++) {
                int nb = wc * 64 + ct * 8;
                unsigned b0 = Bs[(ks + tq) * BS_ST + nb + gq];
                unsigned b1 = Bs[(ks + tq + 4) * BS_ST + nb + gq];
                mma_tf32(acc[0][ct], af[0], b0, b1);
                mma_tf32(acc[1][ct], af[1], b0, b1);
            }
        }
        __syncthreads();
    }

#pragma unroll
    for (int mt = 0; mt < 2; mt++) {
        int r0 = m0 + wr * 32 + mt * 16 + gq;
#pragma unroll
        for (int ct = 0; ct < 8; ct++) {
            int n = wc * 64 + ct * 8 + tq * 2;
            float b0v = 0.f, b1v = 0.f;
            if (bp != nullptr) { b0v = bp[n]; b1v = bp[n + 1]; }
            if (r0 < M) {
                float2 o = make_float2(acc[mt][ct][0] + b0v, acc[mt][ct][1] + b1v);
                *(float2*)&C[(size_t)r0 * 128 + n] = o;
            }
            if (r0 + 8 < M) {
                float2 o = make_float2(acc[mt][ct][2] + b0v, acc[mt][ct][3] + b1v);
                *(float2*)&C[(size_t)(r0 + 8) * 128 + n] = o;
            }
        }
    }
}

// ---------------- aggregation + BN + ReLU + residual (+ optional fused output layer) ----
__global__ __launch_bounds__(256) void k_agg(
    int res_sel, int out_sel,
    const float* __restrict__ bn_g, const float* __restrict__ bn_b,
    const float* __restrict__ bn_m, const float* __restrict__ bn_v,
    int do_out,
    const float* __restrict__ Wl2, const float* __restrict__ Wr2,
    const float* __restrict__ bl2)
{
    const float4* __restrict__ yl  = g_yl;
    const float4* __restrict__ yr  = g_yr;
    const float4* __restrict__ res = buf_ptr(res_sel);
    float4* __restrict__ out       = buf_ptr(out_sel);
    const int* __restrict__ col    = g_col;

    int w = (blockIdx.x * blockDim.x + threadIdx.x) >> 5;
    int lane = threadIdx.x & 31;
    if (w >= NN) return;
    int s0 = g_rowptr[w], s1 = g_rowptr[w + 1];

    float ax = 0.f, ay = 0.f, az = 0.f, aw = 0.f;
    int e = s0;
    for (; e + 3 < s1; e += 4) {
        int sA = clamp_node(col[e]);
        int sB = clamp_node(col[e + 1]);
        int sC = clamp_node(col[e + 2]);
        int sD = clamp_node(col[e + 3]);
        float4 vA = yl[sA * 32 + lane];
        float4 vB = yl[sB * 32 + lane];
        float4 vC = yl[sC * 32 + lane];
        float4 vD = yl[sD * 32 + lane];
        ax += vA.x + vB.x + vC.x + vD.x;
        ay += vA.y + vB.y + vC.y + vD.y;
        az += vA.z + vB.z + vC.z + vD.z;
        aw += vA.w + vB.w + vC.w + vD.w;
    }
    for (; e < s1; e++) {
        int sA = clamp_node(col[e]);
        float4 vA = yl[sA * 32 + lane];
        ax += vA.x; ay += vA.y; az += vA.z; aw += vA.w;
    }

    int deg = s1 - s0;
    float inv = 1.f / (float)(deg > 1 ? deg : 1);
    float4 r = yr[w * 32 + lane];
    int f = lane * 4;
    float gx = bn_g[f], gy = bn_g[f + 1], gz = bn_g[f + 2], gw = bn_g[f + 3];
    float bx = bn_b[f], by = bn_b[f + 1], bz = bn_b[f + 2], bw = bn_b[f + 3];
    float mx = bn_m[f], my = bn_m[f + 1], mz = bn_m[f + 2], mw = bn_m[f + 3];
    float qx = bn_v[f], qy = bn_v[f + 1], qz = bn_v[f + 2], qw = bn_v[f + 3];
    float4 rr = res[w * 32 + lane];

    float sx = gx * rsqrtf(qx + BN_EPS);
    float sy = gy * rsqrtf(qy + BN_EPS);
    float sz = gz * rsqrtf(qz + BN_EPS);
    float sw = gw * rsqrtf(qw + BN_EPS);

    float vx = (ax * inv + r.x - mx) * sx + bx;
    float vy = (ay * inv + r.y - my) * sy + by;
    float vz = (az * inv + r.z - mz) * sz + bz;
    float vw = (aw * inv + r.w - mw) * sw + bw;
    vx = fmaxf(vx, 0.f) + rr.x;
    vy = fmaxf(vy, 0.f) + rr.y;
    vz = fmaxf(vz, 0.f) + rr.z;
    vw = fmaxf(vw, 0.f) + rr.w;

    out[w * 32 + lane] = make_float4(vx, vy, vz, vw);

    if (do_out) {
        float a0 = Wl2[f], a1 = Wl2[f + 1], a2 = Wl2[f + 2], a3 = Wl2[f + 3];
        float b0 = Wl2[128 + f], b1 = Wl2[128 + f + 1], b2 = Wl2[128 + f + 2], b3 = Wl2[128 + f + 3];
        float c0 = Wr2[f], c1 = Wr2[f + 1], c2 = Wr2[f + 2], c3 = Wr2[f + 3];
        float e0 = Wr2[128 + f], e1 = Wr2[128 + f + 1], e2 = Wr2[128 + f + 2], e3 = Wr2[128 + f + 3];
        float d0 = vx * a0 + vy * a1 + vz * a2 + vw * a3;
        float d1 = vx * b0 + vy * b1 + vz * b2 + vw * b3;
        float d2 = vx * c0 + vy * c1 + vz * c2 + vw * c3;
        float d3 = vx * e0 + vy * e1 + vz * e2 + vw * e3;
#pragma unroll
        for (int off = 16; off; off >>= 1) {
            d0 += __shfl_xor_sync(0xffffffffu, d0, off);
            d1 += __shfl_xor_sync(0xffffffffu, d1, off);
            d2 += __shfl_xor_sync(0xffffffffu, d2, off);
            d3 += __shfl_xor_sync(0xffffffffu, d3, off);
        }
        if (lane == 0) {
            g_y2[w] = make_float4(d0, d1, d2 + bl2[0], d3 + bl2[1]);
        }
    }
}

// ---------------- final: aggregate 2-wide logits + root term ----------------
__global__ void k_final(float* __restrict__ out)
{
    int i = blockIdx.x * blockDim.x + threadIdx.x;
    if (i >= NN) return;
    int s0 = g_rowptr[i], s1 = g_rowptr[i + 1];
    float a0 = 0.f, a1 = 0.f;
    int e = s0;
    for (; e + 3 < s1; e += 4) {
        float4 v0 = g_y2[clamp_node(g_col[e])];
        float4 v1 = g_y2[clamp_node(g_col[e + 1])];
        float4 v2 = g_y2[clamp_node(g_col[e + 2])];
        float4 v3 = g_y2[clamp_node(g_col[e + 3])];
        a0 += v0.x + v1.x + v2.x + v3.x;
        a1 += v0.y + v1.y + v2.y + v3.y;
    }
    for (; e < s1; e++) {
        float4 v = g_y2[clamp_node(g_col[e])];
        a0 += v.x;
        a1 += v.y;
    }
    int deg = s1 - s0;
    float inv = 1.f / (float)(deg > 1 ? deg : 1);
    float4 self = g_y2[i];
    out[2 * i + 0] = a0 * inv + self.z;
    out[2 * i + 1] = a1 * inv + self.w;
}

// ---------------- launch ----------------
extern "C" void kernel_launch(void* const* d_in, const int* in_sizes, int n_in,
                              void* d_out, int out_size)
{
    const float* x     = (const float*)d_in[0];
    const void*  ei    = (const void*)d_in[1];
    const float* Wl0   = (const float*)d_in[2];
    const float* bl0   = (const float*)d_in[3];
    const float* Wr0   = (const float*)d_in[4];
    const float* Wl1   = (const float*)d_in[5];
    const float* bl1   = (const float*)d_in[6];
    const float* Wr1   = (const float*)d_in[7];
    const float* Wl2   = (const float*)d_in[8];
    const float* bl2   = (const float*)d_in[9];
    const float* Wr2   = (const float*)d_in[10];
    const float* Wres0 = (const float*)d_in[11];
    const float* bn0_g = (const float*)d_in[12];
    const float* bn0_b = (const float*)d_in[13];
    const float* bn0_m = (const float*)d_in[14];
    const float* bn0_v = (const float*)d_in[15];
    const float* bn1_g = (const float*)d_in[16];
    const float* bn1_b = (const float*)d_in[17];
    const float* bn1_m = (const float*)d_in[18];
    const float* bn1_v = (const float*)d_in[19];

    const int off0l = 0;
    const int off0r = IN_DIM * HID;
    const int off0s = 2 * IN_DIM * HID;
    const int off1l = 3 * IN_DIM * HID;
    const int off1r = 3 * IN_DIM * HID + HID * HID;

    // side stream for the dense branch (host objects only; no device allocation)
    cudaStream_t s2;
    cudaStreamCreateWithFlags(&s2, cudaStreamNonBlocking);
    cudaEvent_t evFork, evJoin;
    cudaEventCreateWithFlags(&evFork, cudaEventDisableTiming);
    cudaEventCreateWithFlags(&evJoin, cudaEventDisableTiming);

    // fork: s2 branches off the capture (default) stream
    cudaEventRecord(evFork, 0);
    cudaStreamWaitEvent(s2, evFork, 0);

    // ---- branch B (s2): weight transposes + layer-0 triple GEMM ----
    int tw0 = HID * IN_DIM, tw1 = HID * HID;
    k_transpose<<<(tw0 + 255) / 256, 256, 0, s2>>>(Wl0,   off0l, HID, IN_DIM);
    k_transpose<<<(tw0 + 255) / 256, 256, 0, s2>>>(Wr0,   off0r, HID, IN_DIM);
    k_transpose<<<(tw0 + 255) / 256, 256, 0, s2>>>(Wres0, off0s, HID, IN_DIM);
    k_transpose<<<(tw1 + 255) / 256, 256, 0, s2>>>(Wl1,   off1l, HID, HID);
    k_transpose<<<(tw1 + 255) / 256, 256, 0, s2>>>(Wr1,   off1r, HID, HID);
    int gx = (NN + 127) / 128;
    k_gemm_tc<<<dim3(gx, 3), 256, 0, s2>>>(x, -1, off0l, off0r, off0s,
                                           BUF_YL, BUF_YR, BUF_RES, bl0, NN, IN_DIM);
    cudaEventRecord(evJoin, s2);

    // ---- branch A (default): CSR build ----
    k_detect<<<1, 32>>>((const int*)ei);
    k_zero_deg<<<(NN + 255) / 256, 256>>>();
    e_cvt_hist<<<(NE + 255) / 256, 256>>>(ei);
    k_scan1<<<SCAN_NB, 256>>>();
    k_scan2<<<1, 256>>>();
    k_scan3<<<SCAN_NB, 256>>>();
    k_scatter<<<(NE + 255) / 256, 256>>>();

    // join: default stream waits for the dense branch
    cudaStreamWaitEvent(0, evJoin, 0);

    int agg_blocks = (NN * 32 + 255) / 256;

    // layer 0 aggregate
    k_agg<<<agg_blocks, 256>>>(BUF_RES, BUF_H1, bn0_g, bn0_b, bn0_m, bn0_v,
                               0, nullptr, nullptr, nullptr);

    // layer 1: fused 2-weight GEMM, then aggregate + fused output layer
    k_gemm_tc<<<dim3(gx, 2), 256>>>(nullptr, BUF_H1, off1l, off1r, off1r,
                                    BUF_YL, BUF_YR, BUF_YR, bl1, NN, HID);
    k_agg<<<agg_blocks, 256>>>(BUF_H1, BUF_H2, bn1_g, bn1_b, bn1_m, bn1_v,
                               1, Wl2, Wr2, bl2);

    // final 2-wide aggregation
    k_final<<<(NN + 255) / 256, 256>>>((float*)d_out);
}

// round 8
// speedup vs baseline: 2.0292x; 1.0395x over previous
#include <cuda_runtime.h>
#include <cuda_bf16.h>

#define NN 50000
#define NE 800000
#define IN_DIM 166
#define HID 128
#define BN_EPS 1e-5f
#define SCAN_NB 196   // ceil(NN/256)
#define H0 25088      // node split point (multiple of 128)

// ---------------- scratch ----------------
__device__ int    g_is64;
__device__ int    g_deg[NN];
__device__ int    g_rowptr[NN + 1];
__device__ int    g_cursor[NN];
__device__ int    g_bsum[SCAN_NB];
__device__ int    g_src[NE];
__device__ int    g_dst[NE];
__device__ int    g_col[NE];
__device__ float4 g_yl[NN * 32];
__device__ float4 g_yr[NN * 32];
__device__ float4 g_res[NN * 32];
__device__ float4 g_h1[NN * 32];
__device__ float4 g_h2[NN * 32];
__device__ float4 g_y2[NN];
__device__ float4 g_wt[(3 * IN_DIM * HID + 2 * HID * HID) / 4];

#define BUF_YL  0
#define BUF_YR  1
#define BUF_RES 2
#define BUF_H1  3
#define BUF_H2  4
__device__ __forceinline__ float4* buf_ptr(int s) {
    switch (s) {
        case BUF_YL:  return g_yl;
        case BUF_YR:  return g_yr;
        case BUF_RES: return g_res;
        case BUF_H1:  return g_h1;
        default:      return g_h2;
    }
}

__device__ __forceinline__ int clamp_node(int v) {
    return v < 0 ? 0 : (v >= NN ? NN - 1 : v);
}

// ---------------- tf32 helpers ----------------
__device__ __forceinline__ unsigned f2tf32(float f) {
    unsigned r;
    asm("cvt.rna.tf32.f32 %0, %1;" : "=r"(r) : "f"(f));
    return r;
}
__device__ __forceinline__ void mma_tf32(float c[4], const unsigned a[4],
                                         unsigned b0, unsigned b1) {
    asm("mma.sync.aligned.m16n8k8.row.col.f32.tf32.tf32.f32 "
        "{%0,%1,%2,%3}, {%4,%5,%6,%7}, {%8,%9}, {%0,%1,%2,%3};"
        : "+f"(c[0]), "+f"(c[1]), "+f"(c[2]), "+f"(c[3])
        : "r"(a[0]), "r"(a[1]), "r"(a[2]), "r"(a[3]), "r"(b0), "r"(b1));
}

// ---------------- dtype detection ----------------
__global__ void k_detect(const int* __restrict__ w) {
    if (threadIdx.x == 0 && blockIdx.x == 0) {
        int all_zero = 1;
        for (int t = 0; t < 32; t++) {
            if (w[2 * t + 1] != 0) { all_zero = 0; break; }
        }
        g_is64 = all_zero;
    }
}

__global__ void k_zero_deg() {
    int i = blockIdx.x * blockDim.x + threadIdx.x;
    if (i < NN) g_deg[i] = 0;
}

// ---------------- edge conversion + fused degree histogram ----------------
__global__ void e_cvt_hist(const void* __restrict__ ei) {
    int i = blockIdx.x * blockDim.x + threadIdx.x;
    if (i < NE) {
        int is64 = g_is64;
        int s, d;
        if (is64) {
            s = (int)((const long long*)ei)[i];
            d = (int)((const long long*)ei)[NE + i];
        } else {
            s = ((const int*)ei)[i];
            d = ((const int*)ei)[NE + i];
        }
        s = clamp_node(s);
        d = clamp_node(d);
        g_src[i] = s;
        g_dst[i] = d;
        atomicAdd(&g_deg[d], 1);
    }
}

// ---------------- CSR scan ----------------
__global__ void k_scan1() {
    __shared__ int sm[256];
    int b = blockIdx.x, t = threadIdx.x;
    int i = b * 256 + t;
    int v = (i < NN) ? g_deg[i] : 0;
    sm[t] = v;
    __syncthreads();
    for (int off = 1; off < 256; off <<= 1) {
        int u = (t >= off) ? sm[t - off] : 0;
        __syncthreads();
        sm[t] += u;
        __syncthreads();
    }
    if (i < NN) g_rowptr[i] = sm[t] - v;
    if (t == 255) g_bsum[b] = sm[255];
}

__global__ void k_scan2() {
    __shared__ int sm[256];
    int t = threadIdx.x;
    int v = (t < SCAN_NB) ? g_bsum[t] : 0;
    sm[t] = v;
    __syncthreads();
    for (int off = 1; off < 256; off <<= 1) {
        int u = (t >= off) ? sm[t - off] : 0;
        __syncthreads();
        sm[t] += u;
        __syncthreads();
    }
    if (t < SCAN_NB) g_bsum[t] = sm[t] - v;
}

__global__ void k_scan3() {
    int i = blockIdx.x * blockDim.x + threadIdx.x;
    if (i < NN) {
        int r = g_rowptr[i] + g_bsum[i >> 8];
        g_rowptr[i] = r;
        g_cursor[i] = r;
    }
    if (i == 0) g_rowptr[NN] = NE;
}

__global__ void k_scatter() {
    int i = blockIdx.x * blockDim.x + threadIdx.x;
    if (i < NE) {
        int pos = atomicAdd(&g_cursor[g_dst[i]], 1);
        if (pos >= 0 && pos < NE) g_col[pos] = g_src[i];
    }
}

// ---------------- fused weight transpose (all 5 weights, one launch) ----------------
#define S0 (HID * IN_DIM)   // 21248
#define S1 (HID * HID)      // 16384

__global__ void k_transpose_all(
    const float* __restrict__ Wl0, const float* __restrict__ Wr0,
    const float* __restrict__ Wres0,
    const float* __restrict__ Wl1, const float* __restrict__ Wr1)
{
    float* wt = reinterpret_cast<float*>(g_wt);
    int i = blockIdx.x * blockDim.x + threadIdx.x;
    if (i < 3 * S0) {
        const float* W = (i < S0) ? Wl0 : (i < 2 * S0) ? Wr0 : Wres0;
        int seg = i / S0;
        int j = i - seg * S0;
        int n = j / IN_DIM, k = j % IN_DIM;
        wt[seg * S0 + k * HID + n] = W[j];
    } else {
        int j = i - 3 * S0;
        if (j < 2 * S1) {
            const float* W = (j < S1) ? Wl1 : Wr1;
            int seg = j / S1;
            int jj = j - seg * S1;
            int n = jj / HID, k = jj % HID;
            wt[3 * S0 + seg * S1 + k * HID + n] = W[jj];
        }
    }
}

// ---------------- tf32 tensor-core GEMM (multi-weight via blockIdx.y, row-offset) ------
#define AS_ST 20
#define BS_ST 136

__global__ __launch_bounds__(256) void k_gemm_tc(
    const float* __restrict__ Ax,
    int a_sel, int m_base,
    int woff0, int woff1, int woff2,
    int osel0, int osel1, int osel2,
    const float* __restrict__ bias,    // applied only for blockIdx.y == 1
    int M, int K)
{
    __shared__ unsigned As[128 * AS_ST];
    __shared__ unsigned Bs[16 * BS_ST];

    int yb = blockIdx.y;
    int woff = (yb == 0) ? woff0 : (yb == 1) ? woff1 : woff2;
    int osel = (yb == 0) ? osel0 : (yb == 1) ? osel1 : osel2;
    const float* bp = (yb == 1) ? bias : nullptr;

    const float* A = (a_sel < 0) ? Ax : reinterpret_cast<const float*>(buf_ptr(a_sel));
    float* C = reinterpret_cast<float*>(buf_ptr(osel));
    const float* Wt = reinterpret_cast<const float*>(g_wt) + woff;

    int tid = threadIdx.x;
    int lane = tid & 31, wid = tid >> 5;
    int wr = wid & 3, wc = wid >> 2;
    int m0 = m_base + blockIdx.x * 128;
    int gq = lane >> 2, tq = lane & 3;

    float acc[2][8][4];
#pragma unroll
    for (int mt = 0; mt < 2; mt++)
#pragma unroll
        for (int ct = 0; ct < 8; ct++)
#pragma unroll
            for (int j = 0; j < 4; j++) acc[mt][ct][j] = 0.f;

    int KT = (K + 15) >> 4;
    for (int kt = 0; kt < KT; kt++) {
        int k0 = kt * 16;
#pragma unroll
        for (int i = 0; i < 8; i++) {
            int l = tid + i * 256;
            int k = l & 15, m = l >> 4;
            float v = 0.f;
            int gm = m0 + m, gk = k0 + k;
            if (gm < M && gk < K) v = A[(size_t)gm * K + gk];
            As[m * AS_ST + k] = f2tf32(v);
        }
#pragma unroll
        for (int i = 0; i < 8; i++) {
            int l = tid + i * 256;
            int n = l & 127, k = l >> 7;
            float v = 0.f;
            int gk = k0 + k;
            if (gk < K) v = Wt[(size_t)gk * 128 + n];
            Bs[k * BS_ST + n] = f2tf32(v);
        }
        __syncthreads();
#pragma unroll
        for (int ks = 0; ks < 16; ks += 8) {
            unsigned af[2][4];
#pragma unroll
            for (int mt = 0; mt < 2; mt++) {
                int mb = wr * 32 + mt * 16;
                af[mt][0] = As[(mb + gq) * AS_ST + ks + tq];
                af[mt][1] = As[(mb + gq + 8) * AS_ST + ks + tq];
                af[mt][2] = As[(mb + gq) * AS_ST + ks + tq + 4];
                af[mt][3] = As[(mb + gq + 8) * AS_ST + ks + tq + 4];
            }
#pragma unroll
            for (int ct = 0; ct < 8; ct++) {
                int nb = wc * 64 + ct * 8;
                unsigned b0 = Bs[(ks + tq) * BS_ST + nb + gq];
                unsigned b1 = Bs[(ks + tq + 4) * BS_ST + nb + gq];
                mma_tf32(acc[0][ct], af[0], b0, b1);
                mma_tf32(acc[1][ct], af[1], b0, b1);
            }
        }
        __syncthreads();
    }

#pragma unroll
    for (int mt = 0; mt < 2; mt++) {
        int r0 = m0 + wr * 32 + mt * 16 + gq;
#pragma unroll
        for (int ct = 0; ct < 8; ct++) {
            int n = wc * 64 + ct * 8 + tq * 2;
            float b0v = 0.f, b1v = 0.f;
            if (bp != nullptr) { b0v = bp[n]; b1v = bp[n + 1]; }
            if (r0 < M) {
                float2 o = make_float2(acc[mt][ct][0] + b0v, acc[mt][ct][1] + b1v);
                *(float2*)&C[(size_t)r0 * 128 + n] = o;
            }
            if (r0 + 8 < M) {
                float2 o = make_float2(acc[mt][ct][2] + b0v, acc[mt][ct][3] + b1v);
                *(float2*)&C[(size_t)(r0 + 8) * 128 + n] = o;
            }
        }
    }
}

// ---------------- aggregation + BN + ReLU + residual (+ optional fused output layer) ----
__global__ __launch_bounds__(256) void k_agg(
    int n0, int n1,
    int res_sel, int out_sel,
    const float* __restrict__ bn_g, const float* __restrict__ bn_b,
    const float* __restrict__ bn_m, const float* __restrict__ bn_v,
    int do_out,
    const float* __restrict__ Wl2, const float* __restrict__ Wr2,
    const float* __restrict__ bl2)
{
    const float4* __restrict__ yl  = g_yl;
    const float4* __restrict__ yr  = g_yr;
    const float4* __restrict__ res = buf_ptr(res_sel);
    float4* __restrict__ out       = buf_ptr(out_sel);
    const int* __restrict__ col    = g_col;

    int w = n0 + ((blockIdx.x * blockDim.x + threadIdx.x) >> 5);
    int lane = threadIdx.x & 31;
    if (w >= n1) return;
    int s0 = g_rowptr[w], s1 = g_rowptr[w + 1];

    float ax = 0.f, ay = 0.f, az = 0.f, aw = 0.f;
    int e = s0;
    for (; e + 3 < s1; e += 4) {
        int sA = clamp_node(col[e]);
        int sB = clamp_node(col[e + 1]);
        int sC = clamp_node(col[e + 2]);
        int sD = clamp_node(col[e + 3]);
        float4 vA = yl[sA * 32 + lane];
        float4 vB = yl[sB * 32 + lane];
        float4 vC = yl[sC * 32 + lane];
        float4 vD = yl[sD * 32 + lane];
        ax += vA.x + vB.x + vC.x + vD.x;
        ay += vA.y + vB.y + vC.y + vD.y;
        az += vA.z + vB.z + vC.z + vD.z;
        aw += vA.w + vB.w + vC.w + vD.w;
    }
    for (; e < s1; e++) {
        int sA = clamp_node(col[e]);
        float4 vA = yl[sA * 32 + lane];
        ax += vA.x; ay += vA.y; az += vA.z; aw += vA.w;
    }

    int deg = s1 - s0;
    float inv = 1.f / (float)(deg > 1 ? deg : 1);
    float4 r = yr[w * 32 + lane];
    int f = lane * 4;
    float gx = bn_g[f], gy = bn_g[f + 1], gz = bn_g[f + 2], gw = bn_g[f + 3];
    float bx = bn_b[f], by = bn_b[f + 1], bz = bn_b[f + 2], bw = bn_b[f + 3];
    float mx = bn_m[f], my = bn_m[f + 1], mz = bn_m[f + 2], mw = bn_m[f + 3];
    float qx = bn_v[f], qy = bn_v[f + 1], qz = bn_v[f + 2], qw = bn_v[f + 3];
    float4 rr = res[w * 32 + lane];

    float sx = gx * rsqrtf(qx + BN_EPS);
    float sy = gy * rsqrtf(qy + BN_EPS);
    float sz = gz * rsqrtf(qz + BN_EPS);
    float sw = gw * rsqrtf(qw + BN_EPS);

    float vx = (ax * inv + r.x - mx) * sx + bx;
    float vy = (ay * inv + r.y - my) * sy + by;
    float vz = (az * inv + r.z - mz) * sz + bz;
    float vw = (aw * inv + r.w - mw) * sw + bw;
    vx = fmaxf(vx, 0.f) + rr.x;
    vy = fmaxf(vy, 0.f) + rr.y;
    vz = fmaxf(vz, 0.f) + rr.z;
    vw = fmaxf(vw, 0.f) + rr.w;

    out[w * 32 + lane] = make_float4(vx, vy, vz, vw);

    if (do_out) {
        float a0 = Wl2[f], a1 = Wl2[f + 1], a2 = Wl2[f + 2], a3 = Wl2[f + 3];
        float b0 = Wl2[128 + f], b1 = Wl2[128 + f + 1], b2 = Wl2[128 + f + 2], b3 = Wl2[128 + f + 3];
        float c0 = Wr2[f], c1 = Wr2[f + 1], c2 = Wr2[f + 2], c3 = Wr2[f + 3];
        float e0 = Wr2[128 + f], e1 = Wr2[128 + f + 1], e2 = Wr2[128 + f + 2], e3 = Wr2[128 + f + 3];
        float d0 = vx * a0 + vy * a1 + vz * a2 + vw * a3;
        float d1 = vx * b0 + vy * b1 + vz * b2 + vw * b3;
        float d2 = vx * c0 + vy * c1 + vz * c2 + vw * c3;
        float d3 = vx * e0 + vy * e1 + vz * e2 + vw * e3;
#pragma unroll
        for (int off = 16; off; off >>= 1) {
            d0 += __shfl_xor_sync(0xffffffffu, d0, off);
            d1 += __shfl_xor_sync(0xffffffffu, d1, off);
            d2 += __shfl_xor_sync(0xffffffffu, d2, off);
            d3 += __shfl_xor_sync(0xffffffffu, d3, off);
        }
        if (lane == 0) {
            g_y2[w] = make_float4(d0, d1, d2 + bl2[0], d3 + bl2[1]);
        }
    }
}

// ---------------- final: aggregate 2-wide logits + root term ----------------
__global__ void k_final(float* __restrict__ out)
{
    int i = blockIdx.x * blockDim.x + threadIdx.x;
    if (i >= NN) return;
    int s0 = g_rowptr[i], s1 = g_rowptr[i + 1];
    float a0 = 0.f, a1 = 0.f;
    int e = s0;
    for (; e + 3 < s1; e += 4) {
        float4 v0 = g_y2[clamp_node(g_col[e])];
        float4 v1 = g_y2[clamp_node(g_col[e + 1])];
        float4 v2 = g_y2[clamp_node(g_col[e + 2])];
        float4 v3 = g_y2[clamp_node(g_col[e + 3])];
        a0 += v0.x + v1.x + v2.x + v3.x;
        a1 += v0.y + v1.y + v2.y + v3.y;
    }
    for (; e < s1; e++) {
        float4 v = g_y2[clamp_node(g_col[e])];
        a0 += v.x;
        a1 += v.y;
    }
    int deg = s1 - s0;
    float inv = 1.f / (float)(deg > 1 ? deg : 1);
    float4 self = g_y2[i];
    out[2 * i + 0] = a0 * inv + self.z;
    out[2 * i + 1] = a1 * inv + self.w;
}

// ---------------- launch ----------------
extern "C" void kernel_launch(void* const* d_in, const int* in_sizes, int n_in,
                              void* d_out, int out_size)
{
    const float* x     = (const float*)d_in[0];
    const void*  ei    = (const void*)d_in[1];
    const float* Wl0   = (const float*)d_in[2];
    const float* bl0   = (const float*)d_in[3];
    const float* Wr0   = (const float*)d_in[4];
    const float* Wl1   = (const float*)d_in[5];
    const float* bl1   = (const float*)d_in[6];
    const float* Wr1   = (const float*)d_in[7];
    const float* Wl2   = (const float*)d_in[8];
    const float* bl2   = (const float*)d_in[9];
    const float* Wr2   = (const float*)d_in[10];
    const float* Wres0 = (const float*)d_in[11];
    const float* bn0_g = (const float*)d_in[12];
    const float* bn0_b = (const float*)d_in[13];
    const float* bn0_m = (const float*)d_in[14];
    const float* bn0_v = (const float*)d_in[15];
    const float* bn1_g = (const float*)d_in[16];
    const float* bn1_b = (const float*)d_in[17];
    const float* bn1_m = (const float*)d_in[18];
    const float* bn1_v = (const float*)d_in[19];

    const int off0l = 0;
    const int off0r = S0;
    const int off0s = 2 * S0;
    const int off1l = 3 * S0;
    const int off1r = 3 * S0 + S1;

    cudaStream_t s2;
    cudaStreamCreateWithFlags(&s2, cudaStreamNonBlocking);
    cudaEvent_t evFork, evDense, evCSR, evHalf1;
    cudaEventCreateWithFlags(&evFork,  cudaEventDisableTiming);
    cudaEventCreateWithFlags(&evDense, cudaEventDisableTiming);
    cudaEventCreateWithFlags(&evCSR,   cudaEventDisableTiming);
    cudaEventCreateWithFlags(&evHalf1, cudaEventDisableTiming);

    // fork
    cudaEventRecord(evFork, 0);
    cudaStreamWaitEvent(s2, evFork, 0);

    // ---- dense branch (s2): fused transpose + layer-0 triple GEMM ----
    int ttotal = 3 * S0 + 2 * S1;
    k_transpose_all<<<(ttotal + 255) / 256, 256, 0, s2>>>(Wl0, Wr0, Wres0, Wl1, Wr1);
    int gx_all = (NN + 127) / 128;   // 391
    k_gemm_tc<<<dim3(gx_all, 3), 256, 0, s2>>>(x, -1, 0, off0l, off0r, off0s,
                                               BUF_YL, BUF_YR, BUF_RES, bl0, NN, IN_DIM);
    cudaEventRecord(evDense, s2);

    // ---- CSR branch (default) ----
    k_detect<<<1, 32>>>((const int*)ei);
    k_zero_deg<<<(NN + 255) / 256, 256>>>();
    e_cvt_hist<<<(NE + 255) / 256, 256>>>(ei);
    k_scan1<<<SCAN_NB, 256>>>();
    k_scan2<<<1, 256>>>();
    k_scan3<<<SCAN_NB, 256>>>();
    k_scatter<<<(NE + 255) / 256, 256>>>();
    cudaEventRecord(evCSR, 0);

    // cross joins: s0 gets dense, s2 gets CSR
    cudaStreamWaitEvent(0, evDense, 0);
    cudaStreamWaitEvent(s2, evCSR, 0);

    // ---- pipelined layer-0 agg + layer-1 GEMM, split by node halves ----
    int blk_h0 = (H0 * 32 + 255) / 256;
    int blk_h1 = ((NN - H0) * 32 + 255) / 256;
    int gx_h0 = H0 / 128;                    // 196
    int gx_h1 = (NN - H0 + 127) / 128;       // 195

    // half0 on default stream
    k_agg<<<blk_h0, 256>>>(0, H0, BUF_RES, BUF_H1, bn0_g, bn0_b, bn0_m, bn0_v,
                           0, nullptr, nullptr, nullptr);
    k_gemm_tc<<<dim3(gx_h0, 2), 256>>>(nullptr, BUF_H1, 0, off1l, off1r, off1r,
                                       BUF_YL, BUF_YR, BUF_YR, bl1, NN, HID);
    // half1 on s2
    k_agg<<<blk_h1, 256, 0, s2>>>(H0, NN, BUF_RES, BUF_H1, bn0_g, bn0_b, bn0_m, bn0_v,
                                  0, nullptr, nullptr, nullptr);
    k_gemm_tc<<<dim3(gx_h1, 2), 256, 0, s2>>>(nullptr, BUF_H1, H0, off1l, off1r, off1r,
                                              BUF_YL, BUF_YR, BUF_YR, bl1, NN, HID);
    cudaEventRecord(evHalf1, s2);
    cudaStreamWaitEvent(0, evHalf1, 0);

    // ---- layer-1 aggregate + fused output layer, then final ----
    int blk_all = (NN * 32 + 255) / 256;
    k_agg<<<blk_all, 256>>>(0, NN, BUF_H1, BUF_H2, bn1_g, bn1_b, bn1_m, bn1_v,
                            1, Wl2, Wr2, bl2);
    k_final<<<(NN + 255) / 256, 256>>>((float*)d_out);
}

// round 9
// speedup vs baseline: 2.0338x; 1.0023x over previous
#include <cuda_runtime.h>
#include <cuda_bf16.h>

#define NN 50000
#define NE 800000
#define IN_DIM 166
#define HID 128
#define BN_EPS 1e-5f
#define SCAN_NB 196   // ceil(NN/256)
#define H0 25088      // node split point (multiple of 128)

// ---------------- scratch ----------------
__device__ int    g_deg[NN];           // statically zero-initialized; scan1 re-zeroes after use
__device__ int    g_rowptr[NN + 1];
__device__ int    g_cursor[NN];
__device__ int    g_bsum[SCAN_NB];
__device__ int    g_src[NE];
__device__ int    g_dst[NE];
__device__ int    g_col[NE];
__device__ float4 g_yl[NN * 32];
__device__ float4 g_yr[NN * 32];
__device__ float4 g_res[NN * 32];
__device__ float4 g_h1[NN * 32];
__device__ float4 g_h2[NN * 32];
__device__ float4 g_y2[NN];
__device__ float4 g_wt[(3 * IN_DIM * HID + 2 * HID * HID) / 4];

#define BUF_YL  0
#define BUF_YR  1
#define BUF_RES 2
#define BUF_H1  3
#define BUF_H2  4
__device__ __forceinline__ float4* buf_ptr(int s) {
    switch (s) {
        case BUF_YL:  return g_yl;
        case BUF_YR:  return g_yr;
        case BUF_RES: return g_res;
        case BUF_H1:  return g_h1;
        default:      return g_h2;
    }
}

__device__ __forceinline__ int clamp_node(int v) {
    return v < 0 ? 0 : (v >= NN ? NN - 1 : v);
}

// ---------------- tf32 helpers ----------------
__device__ __forceinline__ unsigned f2tf32(float f) {
    unsigned r;
    asm("cvt.rna.tf32.f32 %0, %1;" : "=r"(r) : "f"(f));
    return r;
}
__device__ __forceinline__ void mma_tf32(float c[4], const unsigned a[4],
                                         unsigned b0, unsigned b1) {
    asm("mma.sync.aligned.m16n8k8.row.col.f32.tf32.tf32.f32 "
        "{%0,%1,%2,%3}, {%4,%5,%6,%7}, {%8,%9}, {%0,%1,%2,%3};"
        : "+f"(c[0]), "+f"(c[1]), "+f"(c[2]), "+f"(c[3])
        : "r"(a[0]), "r"(a[1]), "r"(a[2]), "r"(a[3]), "r"(b0), "r"(b1));
}

// ---------------- edge conversion + inline dtype detect + fused degree histogram ------
__global__ void e_cvt_hist(const void* __restrict__ ei) {
    __shared__ int sh_is64;
    if (threadIdx.x == 0) {
        const int* w = (const int*)ei;
        int all_zero = 1;
        for (int t = 0; t < 32; t++) {
            if (w[2 * t + 1] != 0) { all_zero = 0; break; }
        }
        sh_is64 = all_zero;
    }
    __syncthreads();
    int is64 = sh_is64;
    int i = blockIdx.x * blockDim.x + threadIdx.x;
    if (i < NE) {
        int s, d;
        if (is64) {
            s = (int)((const long long*)ei)[i];
            d = (int)((const long long*)ei)[NE + i];
        } else {
            s = ((const int*)ei)[i];
            d = ((const int*)ei)[NE + i];
        }
        s = clamp_node(s);
        d = clamp_node(d);
        g_src[i] = s;
        g_dst[i] = d;
        atomicAdd(&g_deg[d], 1);
    }
}

// ---------------- CSR scan (2 kernels) ----------------
__global__ void k_scan1() {
    __shared__ int sm[256];
    int b = blockIdx.x, t = threadIdx.x;
    int i = b * 256 + t;
    int v = (i < NN) ? g_deg[i] : 0;
    if (i < NN) g_deg[i] = 0;   // restore zeros for the next replay
    sm[t] = v;
    __syncthreads();
    for (int off = 1; off < 256; off <<= 1) {
        int u = (t >= off) ? sm[t - off] : 0;
        __syncthreads();
        sm[t] += u;
        __syncthreads();
    }
    if (i < NN) g_rowptr[i] = sm[t] - v;   // local exclusive
    if (t == 255) g_bsum[b] = sm[255];
}

// scan of 196 block sums (redundant per block) + offset add + cursor init
__global__ void k_scan23() {
    __shared__ int sm[256];
    int t = threadIdx.x;
    int b = blockIdx.x;
    int v = (t < SCAN_NB) ? g_bsum[t] : 0;
    sm[t] = v;
    __syncthreads();
    for (int off = 1; off < 256; off <<= 1) {
        int u = (t >= off) ? sm[t - off] : 0;
        __syncthreads();
        sm[t] += u;
        __syncthreads();
    }
    __shared__ int sh_boff;
    if (t == 0) sh_boff = sm[b] - g_bsum[b];   // exclusive prefix for this block
    __syncthreads();
    int boff = sh_boff;
    int i = b * 256 + t;
    if (i < NN) {
        int r = g_rowptr[i] + boff;
        g_rowptr[i] = r;
        g_cursor[i] = r;
    }
    if (i == 0) g_rowptr[NN] = NE;
}

__global__ void k_scatter() {
    int i = blockIdx.x * blockDim.x + threadIdx.x;
    if (i < NE) {
        int pos = atomicAdd(&g_cursor[g_dst[i]], 1);
        if (pos >= 0 && pos < NE) g_col[pos] = g_src[i];
    }
}

// ---------------- fused weight transpose (all 5 weights, one launch) ----------------
#define S0 (HID * IN_DIM)   // 21248
#define S1 (HID * HID)      // 16384

__global__ void k_transpose_all(
    const float* __restrict__ Wl0, const float* __restrict__ Wr0,
    const float* __restrict__ Wres0,
    const float* __restrict__ Wl1, const float* __restrict__ Wr1)
{
    float* wt = reinterpret_cast<float*>(g_wt);
    int i = blockIdx.x * blockDim.x + threadIdx.x;
    if (i < 3 * S0) {
        const float* W = (i < S0) ? Wl0 : (i < 2 * S0) ? Wr0 : Wres0;
        int seg = i / S0;
        int j = i - seg * S0;
        int n = j / IN_DIM, k = j % IN_DIM;
        wt[seg * S0 + k * HID + n] = W[j];
    } else {
        int j = i - 3 * S0;
        if (j < 2 * S1) {
            const float* W = (j < S1) ? Wl1 : Wr1;
            int seg = j / S1;
            int jj = j - seg * S1;
            int n = jj / HID, k = jj % HID;
            wt[3 * S0 + seg * S1 + k * HID + n] = W[jj];
        }
    }
}

// ---------------- tf32 tensor-core GEMM (multi-weight via blockIdx.y, row-offset) ------
#define AS_ST 20
#define BS_ST 136

__global__ __launch_bounds__(256) void k_gemm_tc(
    const float* __restrict__ Ax,
    int a_sel, int m_base,
    int woff0, int woff1, int woff2,
    int osel0, int osel1, int osel2,
    const float* __restrict__ bias,    // applied only for blockIdx.y == 1
    int M, int K)
{
    __shared__ unsigned As[128 * AS_ST];
    __shared__ unsigned Bs[16 * BS_ST];

    int yb = blockIdx.y;
    int woff = (yb == 0) ? woff0 : (yb == 1) ? woff1 : woff2;
    int osel = (yb == 0) ? osel0 : (yb == 1) ? osel1 : osel2;
    const float* bp = (yb == 1) ? bias : nullptr;

    const float* A = (a_sel < 0) ? Ax : reinterpret_cast<const float*>(buf_ptr(a_sel));
    float* C = reinterpret_cast<float*>(buf_ptr(osel));
    const float* Wt = reinterpret_cast<const float*>(g_wt) + woff;

    int tid = threadIdx.x;
    int lane = tid & 31, wid = tid >> 5;
    int wr = wid & 3, wc = wid >> 2;
    int m0 = m_base + blockIdx.x * 128;
    int gq = lane >> 2, tq = lane & 3;

    float acc[2][8][4];
#pragma unroll
    for (int mt = 0; mt < 2; mt++)
#pragma unroll
        for (int ct = 0; ct < 8; ct++)
#pragma unroll
            for (int j = 0; j < 4; j++) acc[mt][ct][j] = 0.f;

    int KT = (K + 15) >> 4;
    for (int kt = 0; kt < KT; kt++) {
        int k0 = kt * 16;
#pragma unroll
        for (int i = 0; i < 8; i++) {
            int l = tid + i * 256;
            int k = l & 15, m = l >> 4;
            float v = 0.f;
            int gm = m0 + m, gk = k0 + k;
            if (gm < M && gk < K) v = A[(size_t)gm * K + gk];
            As[m * AS_ST + k] = f2tf32(v);
        }
#pragma unroll
        for (int i = 0; i < 8; i++) {
            int l = tid + i * 256;
            int n = l & 127, k = l >> 7;
            float v = 0.f;
            int gk = k0 + k;
            if (gk < K) v = Wt[(size_t)gk * 128 + n];
            Bs[k * BS_ST + n] = f2tf32(v);
        }
        __syncthreads();
#pragma unroll
        for (int ks = 0; ks < 16; ks += 8) {
            unsigned af[2][4];
#pragma unroll
            for (int mt = 0; mt < 2; mt++) {
                int mb = wr * 32 + mt * 16;
                af[mt][0] = As[(mb + gq) * AS_ST + ks + tq];
                af[mt][1] = As[(mb + gq + 8) * AS_ST + ks + tq];
                af[mt][2] = As[(mb + gq) * AS_ST + ks + tq + 4];
                af[mt][3] = As[(mb + gq + 8) * AS_ST + ks + tq + 4];
            }
#pragma unroll
            for (int ct = 0; ct < 8; ct++) {
                int nb = wc * 64 + ct * 8;
                unsigned b0 = Bs[(ks + tq) * BS_ST + nb + gq];
                unsigned b1 = Bs[(ks + tq + 4) * BS_ST + nb + gq];
                mma_tf32(acc[0][ct], af[0], b0, b1);
                mma_tf32(acc[1][ct], af[1], b0, b1);
            }
        }
        __syncthreads();
    }

#pragma unroll
    for (int mt = 0; mt < 2; mt++) {
        int r0 = m0 + wr * 32 + mt * 16 + gq;
#pragma unroll
        for (int ct = 0; ct < 8; ct++) {
            int n = wc * 64 + ct * 8 + tq * 2;
            float b0v = 0.f, b1v = 0.f;
            if (bp != nullptr) { b0v = bp[n]; b1v = bp[n + 1]; }
            if (r0 < M) {
                float2 o = make_float2(acc[mt][ct][0] + b0v, acc[mt][ct][1] + b1v);
                *(float2*)&C[(size_t)r0 * 128 + n] = o;
            }
            if (r0 + 8 < M) {
                float2 o = make_float2(acc[mt][ct][2] + b0v, acc[mt][ct][3] + b1v);
                *(float2*)&C[(size_t)(r0 + 8) * 128 + n] = o;
            }
        }
    }
}

// ---------------- aggregation + BN + ReLU + residual (+ optional fused output layer) ----
__global__ __launch_bounds__(256) void k_agg(
    int n0, int n1,
    int res_sel, int out_sel,
    const float* __restrict__ bn_g, const float* __restrict__ bn_b,
    const float* __restrict__ bn_m, const float* __restrict__ bn_v,
    int do_out,
    const float* __restrict__ Wl2, const float* __restrict__ Wr2,
    const float* __restrict__ bl2)
{
    const float4* __restrict__ yl  = g_yl;
    const float4* __restrict__ yr  = g_yr;
    const float4* __restrict__ res = buf_ptr(res_sel);
    float4* __restrict__ out       = buf_ptr(out_sel);
    const int* __restrict__ col    = g_col;

    int w = n0 + ((blockIdx.x * blockDim.x + threadIdx.x) >> 5);
    int lane = threadIdx.x & 31;
    if (w >= n1) return;
    int s0 = g_rowptr[w], s1 = g_rowptr[w + 1];

    float ax = 0.f, ay = 0.f, az = 0.f, aw = 0.f;
    int e = s0;
    // 8-way unrolled gather: 8 independent 512B row loads in flight
    for (; e + 7 < s1; e += 8) {
        int si[8];
#pragma unroll
        for (int u = 0; u < 8; u++) si[u] = clamp_node(col[e + u]);
        float4 v0 = yl[si[0] * 32 + lane];
        float4 v1 = yl[si[1] * 32 + lane];
        float4 v2 = yl[si[2] * 32 + lane];
        float4 v3 = yl[si[3] * 32 + lane];
        float4 v4 = yl[si[4] * 32 + lane];
        float4 v5 = yl[si[5] * 32 + lane];
        float4 v6 = yl[si[6] * 32 + lane];
        float4 v7 = yl[si[7] * 32 + lane];
        ax += (v0.x + v1.x) + (v2.x + v3.x) + (v4.x + v5.x) + (v6.x + v7.x);
        ay += (v0.y + v1.y) + (v2.y + v3.y) + (v4.y + v5.y) + (v6.y + v7.y);
        az += (v0.z + v1.z) + (v2.z + v3.z) + (v4.z + v5.z) + (v6.z + v7.z);
        aw += (v0.w + v1.w) + (v2.w + v3.w) + (v4.w + v5.w) + (v6.w + v7.w);
    }
    for (; e + 1 < s1; e += 2) {
        int sA = clamp_node(col[e]);
        int sB = clamp_node(col[e + 1]);
        float4 vA = yl[sA * 32 + lane];
        float4 vB = yl[sB * 32 + lane];
        ax += vA.x + vB.x; ay += vA.y + vB.y;
        az += vA.z + vB.z; aw += vA.w + vB.w;
    }
    if (e < s1) {
        int sA = clamp_node(col[e]);
        float4 vA = yl[sA * 32 + lane];
        ax += vA.x; ay += vA.y; az += vA.z; aw += vA.w;
    }

    int deg = s1 - s0;
    float inv = 1.f / (float)(deg > 1 ? deg : 1);
    float4 r = yr[w * 32 + lane];
    int f = lane * 4;
    float gx = bn_g[f], gy = bn_g[f + 1], gz = bn_g[f + 2], gw = bn_g[f + 3];
    float bx = bn_b[f], by = bn_b[f + 1], bz = bn_b[f + 2], bw = bn_b[f + 3];
    float mx = bn_m[f], my = bn_m[f + 1], mz = bn_m[f + 2], mw = bn_m[f + 3];
    float qx = bn_v[f], qy = bn_v[f + 1], qz = bn_v[f + 2], qw = bn_v[f + 3];
    float4 rr = res[w * 32 + lane];

    float sx = gx * rsqrtf(qx + BN_EPS);
    float sy = gy * rsqrtf(qy + BN_EPS);
    float sz = gz * rsqrtf(qz + BN_EPS);
    float sw = gw * rsqrtf(qw + BN_EPS);

    float vx = (ax * inv + r.x - mx) * sx + bx;
    float vy = (ay * inv + r.y - my) * sy + by;
    float vz = (az * inv + r.z - mz) * sz + bz;
    float vw = (aw * inv + r.w - mw) * sw + bw;
    vx = fmaxf(vx, 0.f) + rr.x;
    vy = fmaxf(vy, 0.f) + rr.y;
    vz = fmaxf(vz, 0.f) + rr.z;
    vw = fmaxf(vw, 0.f) + rr.w;

    out[w * 32 + lane] = make_float4(vx, vy, vz, vw);

    if (do_out) {
        float a0 = Wl2[f], a1 = Wl2[f + 1], a2 = Wl2[f + 2], a3 = Wl2[f + 3];
        float b0 = Wl2[128 + f], b1 = Wl2[128 + f + 1], b2 = Wl2[128 + f + 2], b3 = Wl2[128 + f + 3];
        float c0 = Wr2[f], c1 = Wr2[f + 1], c2 = Wr2[f + 2], c3 = Wr2[f + 3];
        float e0 = Wr2[128 + f], e1 = Wr2[128 + f + 1], e2 = Wr2[128 + f + 2], e3 = Wr2[128 + f + 3];
        float d0 = vx * a0 + vy * a1 + vz * a2 + vw * a3;
        float d1 = vx * b0 + vy * b1 + vz * b2 + vw * b3;
        float d2 = vx * c0 + vy * c1 + vz * c2 + vw * c3;
        float d3 = vx * e0 + vy * e1 + vz * e2 + vw * e3;
#pragma unroll
        for (int off = 16; off; off >>= 1) {
            d0 += __shfl_xor_sync(0xffffffffu, d0, off);
            d1 += __shfl_xor_sync(0xffffffffu, d1, off);
            d2 += __shfl_xor_sync(0xffffffffu, d2, off);
            d3 += __shfl_xor_sync(0xffffffffu, d3, off);
        }
        if (lane == 0) {
            g_y2[w] = make_float4(d0, d1, d2 + bl2[0], d3 + bl2[1]);
        }
    }
}

// ---------------- final: aggregate 2-wide logits + root term ----------------
__global__ void k_final(float* __restrict__ out)
{
    int i = blockIdx.x * blockDim.x + threadIdx.x;
    if (i >= NN) return;
    int s0 = g_rowptr[i], s1 = g_rowptr[i + 1];
    float a0 = 0.f, a1 = 0.f;
    int e = s0;
    for (; e + 3 < s1; e += 4) {
        float4 v0 = g_y2[clamp_node(g_col[e])];
        float4 v1 = g_y2[clamp_node(g_col[e + 1])];
        float4 v2 = g_y2[clamp_node(g_col[e + 2])];
        float4 v3 = g_y2[clamp_node(g_col[e + 3])];
        a0 += v0.x + v1.x + v2.x + v3.x;
        a1 += v0.y + v1.y + v2.y + v3.y;
    }
    for (; e < s1; e++) {
        float4 v = g_y2[clamp_node(g_col[e])];
        a0 += v.x;
        a1 += v.y;
    }
    int deg = s1 - s0;
    float inv = 1.f / (float)(deg > 1 ? deg : 1);
    float4 self = g_y2[i];
    out[2 * i + 0] = a0 * inv + self.z;
    out[2 * i + 1] = a1 * inv + self.w;
}

// ---------------- launch ----------------
extern "C" void kernel_launch(void* const* d_in, const int* in_sizes, int n_in,
                              void* d_out, int out_size)
{
    const float* x     = (const float*)d_in[0];
    const void*  ei    = (const void*)d_in[1];
    const float* Wl0   = (const float*)d_in[2];
    const float* bl0   = (const float*)d_in[3];
    const float* Wr0   = (const float*)d_in[4];
    const float* Wl1   = (const float*)d_in[5];
    const float* bl1   = (const float*)d_in[6];
    const float* Wr1   = (const float*)d_in[7];
    const float* Wl2   = (const float*)d_in[8];
    const float* bl2   = (const float*)d_in[9];
    const float* Wr2   = (const float*)d_in[10];
    const float* Wres0 = (const float*)d_in[11];
    const float* bn0_g = (const float*)d_in[12];
    const float* bn0_b = (const float*)d_in[13];
    const float* bn0_m = (const float*)d_in[14];
    const float* bn0_v = (const float*)d_in[15];
    const float* bn1_g = (const float*)d_in[16];
    const float* bn1_b = (const float*)d_in[17];
    const float* bn1_m = (const float*)d_in[18];
    const float* bn1_v = (const float*)d_in[19];

    const int off0l = 0;
    const int off0r = S0;
    const int off0s = 2 * S0;
    const int off1l = 3 * S0;
    const int off1r = 3 * S0 + S1;

    cudaStream_t s2;
    cudaStreamCreateWithFlags(&s2, cudaStreamNonBlocking);
    cudaEvent_t evFork, evDense, evCSR, evHalf1;
    cudaEventCreateWithFlags(&evFork,  cudaEventDisableTiming);
    cudaEventCreateWithFlags(&evDense, cudaEventDisableTiming);
    cudaEventCreateWithFlags(&evCSR,   cudaEventDisableTiming);
    cudaEventCreateWithFlags(&evHalf1, cudaEventDisableTiming);

    // fork
    cudaEventRecord(evFork, 0);
    cudaStreamWaitEvent(s2, evFork, 0);

    // ---- CSR branch (default), launches 1-4 ----
    e_cvt_hist<<<(NE + 255) / 256, 256>>>(ei);
    k_scan1<<<SCAN_NB, 256>>>();
    k_scan23<<<SCAN_NB, 256>>>();
    k_scatter<<<(NE + 255) / 256, 256>>>();
    cudaEventRecord(evCSR, 0);

    // ---- dense branch (s2): launches 5-6 (gemm0 = capture launch #6 for ncu) ----
    int ttotal = 3 * S0 + 2 * S1;
    k_transpose_all<<<(ttotal + 255) / 256, 256, 0, s2>>>(Wl0, Wr0, Wres0, Wl1, Wr1);
    int gx_all = (NN + 127) / 128;
    k_gemm_tc<<<dim3(gx_all, 3), 256, 0, s2>>>(x, -1, 0, off0l, off0r, off0s,
                                               BUF_YL, BUF_YR, BUF_RES, bl0, NN, IN_DIM);
    cudaEventRecord(evDense, s2);

    // cross joins
    cudaStreamWaitEvent(0, evDense, 0);
    cudaStreamWaitEvent(s2, evCSR, 0);

    // ---- pipelined layer-0 agg + layer-1 GEMM, split by node halves ----
    int blk_h0 = (H0 * 32 + 255) / 256;
    int blk_h1 = ((NN - H0) * 32 + 255) / 256;
    int gx_h0 = H0 / 128;
    int gx_h1 = (NN - H0 + 127) / 128;

    k_agg<<<blk_h0, 256>>>(0, H0, BUF_RES, BUF_H1, bn0_g, bn0_b, bn0_m, bn0_v,
                           0, nullptr, nullptr, nullptr);
    k_gemm_tc<<<dim3(gx_h0, 2), 256>>>(nullptr, BUF_H1, 0, off1l, off1r, off1r,
                                       BUF_YL, BUF_YR, BUF_YR, bl1, NN, HID);
    k_agg<<<blk_h1, 256, 0, s2>>>(H0, NN, BUF_RES, BUF_H1, bn0_g, bn0_b, bn0_m, bn0_v,
                                  0, nullptr, nullptr, nullptr);
    k_gemm_tc<<<dim3(gx_h1, 2), 256, 0, s2>>>(nullptr, BUF_H1, H0, off1l, off1r, off1r,
                                              BUF_YL, BUF_YR, BUF_YR, bl1, NN, HID);
    cudaEventRecord(evHalf1, s2);
    cudaStreamWaitEvent(0, evHalf1, 0);

    // ---- layer-1 aggregate + fused output layer, then final ----
    int blk_all = (NN * 32 + 255) / 256;
    k_agg<<<blk_all, 256>>>(0, NN, BUF_H1, BUF_H2, bn1_g, bn1_b, bn1_m, bn1_v,
                            1, Wl2, Wr2, bl2);
    k_final<<<(NN + 255) / 256, 256>>>((float*)d_out);
}

// round 10
// speedup vs baseline: 2.1013x; 1.0332x over previous
#include <cuda_runtime.h>
#include <cuda_bf16.h>

#define NN 50000
#define NE 800000
#define IN_DIM 166
#define HID 128
#define BN_EPS 1e-5f
#define SCAN_NB 196   // ceil(NN/256)
#define H0 25088      // node split point (multiple of 128)

// ---------------- scratch ----------------
__device__ int    g_deg[NN];           // statically zero-init; scan1 re-zeroes after use
__device__ int    g_rowptr[NN + 1];
__device__ int    g_cursor[NN];
__device__ int    g_bsum[SCAN_NB];
__device__ int    g_src[NE];
__device__ int    g_dst[NE];
__device__ int    g_col[NE];
__device__ uint2  g_ylh[NN * 32];      // [NN,128] bf16 (gather table) — 256 B/row
__device__ float4 g_yr[NN * 32];
__device__ float4 g_res[NN * 32];
__device__ float4 g_h1[NN * 32];
__device__ float4 g_h2[NN * 32];
__device__ float4 g_y2[NN];
__device__ float4 g_wt[(3 * IN_DIM * HID + 2 * HID * HID) / 4];

#define BUF_YR  1
#define BUF_RES 2
#define BUF_H1  3
#define BUF_H2  4
__device__ __forceinline__ float4* buf_ptr(int s) {
    switch (s) {
        case BUF_YR:  return g_yr;
        case BUF_RES: return g_res;
        case BUF_H1:  return g_h1;
        default:      return g_h2;
    }
}

__device__ __forceinline__ int clamp_node(int v) {
    return v < 0 ? 0 : (v >= NN ? NN - 1 : v);
}

// ---------------- tf32 helpers ----------------
__device__ __forceinline__ unsigned f2tf32(float f) {
    unsigned r;
    asm("cvt.rna.tf32.f32 %0, %1;" : "=r"(r) : "f"(f));
    return r;
}
__device__ __forceinline__ void mma_tf32(float c[4], const unsigned a[4],
                                         unsigned b0, unsigned b1) {
    asm("mma.sync.aligned.m16n8k8.row.col.f32.tf32.tf32.f32 "
        "{%0,%1,%2,%3}, {%4,%5,%6,%7}, {%8,%9}, {%0,%1,%2,%3};"
        : "+f"(c[0]), "+f"(c[1]), "+f"(c[2]), "+f"(c[3])
        : "r"(a[0]), "r"(a[1]), "r"(a[2]), "r"(a[3]), "r"(b0), "r"(b1));
}

// ---------------- edge conversion + inline dtype detect + fused degree histogram ------
__global__ void e_cvt_hist(const void* __restrict__ ei) {
    __shared__ int sh_is64;
    if (threadIdx.x == 0) {
        const int* w = (const int*)ei;
        int all_zero = 1;
        for (int t = 0; t < 32; t++) {
            if (w[2 * t + 1] != 0) { all_zero = 0; break; }
        }
        sh_is64 = all_zero;
    }
    __syncthreads();
    int is64 = sh_is64;
    int i = blockIdx.x * blockDim.x + threadIdx.x;
    if (i < NE) {
        int s, d;
        if (is64) {
            s = (int)((const long long*)ei)[i];
            d = (int)((const long long*)ei)[NE + i];
        } else {
            s = ((const int*)ei)[i];
            d = ((const int*)ei)[NE + i];
        }
        s = clamp_node(s);
        d = clamp_node(d);
        g_src[i] = s;
        g_dst[i] = d;
        atomicAdd(&g_deg[d], 1);
    }
}

// ---------------- CSR scan ----------------
__global__ void k_scan1() {
    __shared__ int sm[256];
    int b = blockIdx.x, t = threadIdx.x;
    int i = b * 256 + t;
    int v = (i < NN) ? g_deg[i] : 0;
    if (i < NN) g_deg[i] = 0;   // restore zeros for the next replay
    sm[t] = v;
    __syncthreads();
    for (int off = 1; off < 256; off <<= 1) {
        int u = (t >= off) ? sm[t - off] : 0;
        __syncthreads();
        sm[t] += u;
        __syncthreads();
    }
    if (i < NN) g_rowptr[i] = sm[t] - v;
    if (t == 255) g_bsum[b] = sm[255];
}

__global__ void k_scan23() {
    __shared__ int sm[256];
    int t = threadIdx.x;
    int b = blockIdx.x;
    int v = (t < SCAN_NB) ? g_bsum[t] : 0;
    sm[t] = v;
    __syncthreads();
    for (int off = 1; off < 256; off <<= 1) {
        int u = (t >= off) ? sm[t - off] : 0;
        __syncthreads();
        sm[t] += u;
        __syncthreads();
    }
    __shared__ int sh_boff;
    if (t == 0) sh_boff = sm[b] - g_bsum[b];
    __syncthreads();
    int boff = sh_boff;
    int i = b * 256 + t;
    if (i < NN) {
        int r = g_rowptr[i] + boff;
        g_rowptr[i] = r;
        g_cursor[i] = r;
    }
    if (i == 0) g_rowptr[NN] = NE;
}

__global__ void k_scatter() {
    int i = blockIdx.x * blockDim.x + threadIdx.x;
    if (i < NE) {
        int pos = atomicAdd(&g_cursor[g_dst[i]], 1);
        if (pos >= 0 && pos < NE) g_col[pos] = g_src[i];
    }
}

// ---------------- fused weight transpose ----------------
#define S0 (HID * IN_DIM)   // 21248
#define S1 (HID * HID)      // 16384

__global__ void k_transpose_all(
    const float* __restrict__ Wl0, const float* __restrict__ Wr0,
    const float* __restrict__ Wres0,
    const float* __restrict__ Wl1, const float* __restrict__ Wr1)
{
    float* wt = reinterpret_cast<float*>(g_wt);
    int i = blockIdx.x * blockDim.x + threadIdx.x;
    if (i < 3 * S0) {
        const float* W = (i < S0) ? Wl0 : (i < 2 * S0) ? Wr0 : Wres0;
        int seg = i / S0;
        int j = i - seg * S0;
        int n = j / IN_DIM, k = j % IN_DIM;
        wt[seg * S0 + k * HID + n] = W[j];
    } else {
        int j = i - 3 * S0;
        if (j < 2 * S1) {
            const float* W = (j < S1) ? Wl1 : Wr1;
            int seg = j / S1;
            int jj = j - seg * S1;
            int n = jj / HID, k = jj % HID;
            wt[3 * S0 + seg * S1 + k * HID + n] = W[jj];
        }
    }
}

// ---------------- tf32 tensor-core GEMM (multi-weight via blockIdx.y, row-offset) ------
// yb == 0 writes packed bf16 to g_ylh (the gather table); yb >= 1 writes fp32.
#define AS_ST 20
#define BS_ST 136

__global__ __launch_bounds__(256) void k_gemm_tc(
    const float* __restrict__ Ax,
    int a_sel, int m_base,
    int woff0, int woff1, int woff2,
    int osel1, int osel2,
    const float* __restrict__ bias,    // applied only for blockIdx.y == 1
    int M, int K)
{
    __shared__ unsigned As[128 * AS_ST];
    __shared__ unsigned Bs[16 * BS_ST];

    int yb = blockIdx.y;
    int woff = (yb == 0) ? woff0 : (yb == 1) ? woff1 : woff2;
    const float* bp = (yb == 1) ? bias : nullptr;

    const float* A = (a_sel < 0) ? Ax : reinterpret_cast<const float*>(buf_ptr(a_sel));
    const float* Wt = reinterpret_cast<const float*>(g_wt) + woff;

    int tid = threadIdx.x;
    int lane = tid & 31, wid = tid >> 5;
    int wr = wid & 3, wc = wid >> 2;
    int m0 = m_base + blockIdx.x * 128;
    int gq = lane >> 2, tq = lane & 3;

    float acc[2][8][4];
#pragma unroll
    for (int mt = 0; mt < 2; mt++)
#pragma unroll
        for (int ct = 0; ct < 8; ct++)
#pragma unroll
            for (int j = 0; j < 4; j++) acc[mt][ct][j] = 0.f;

    int KT = (K + 15) >> 4;
    for (int kt = 0; kt < KT; kt++) {
        int k0 = kt * 16;
#pragma unroll
        for (int i = 0; i < 8; i++) {
            int l = tid + i * 256;
            int k = l & 15, m = l >> 4;
            float v = 0.f;
            int gm = m0 + m, gk = k0 + k;
            if (gm < M && gk < K) v = A[(size_t)gm * K + gk];
            As[m * AS_ST + k] = f2tf32(v);
        }
#pragma unroll
        for (int i = 0; i < 8; i++) {
            int l = tid + i * 256;
            int n = l & 127, k = l >> 7;
            float v = 0.f;
            int gk = k0 + k;
            if (gk < K) v = Wt[(size_t)gk * 128 + n];
            Bs[k * BS_ST + n] = f2tf32(v);
        }
        __syncthreads();
#pragma unroll
        for (int ks = 0; ks < 16; ks += 8) {
            unsigned af[2][4];
#pragma unroll
            for (int mt = 0; mt < 2; mt++) {
                int mb = wr * 32 + mt * 16;
                af[mt][0] = As[(mb + gq) * AS_ST + ks + tq];
                af[mt][1] = As[(mb + gq + 8) * AS_ST + ks + tq];
                af[mt][2] = As[(mb + gq) * AS_ST + ks + tq + 4];
                af[mt][3] = As[(mb + gq + 8) * AS_ST + ks + tq + 4];
            }
#pragma unroll
            for (int ct = 0; ct < 8; ct++) {
                int nb = wc * 64 + ct * 8;
                unsigned b0 = Bs[(ks + tq) * BS_ST + nb + gq];
                unsigned b1 = Bs[(ks + tq + 4) * BS_ST + nb + gq];
                mma_tf32(acc[0][ct], af[0], b0, b1);
                mma_tf32(acc[1][ct], af[1], b0, b1);
            }
        }
        __syncthreads();
    }

    if (yb == 0) {
        // bf16 epilogue into the gather table (2 adjacent cols -> one bf16x2 word)
        unsigned* ylh = reinterpret_cast<unsigned*>(g_ylh);
#pragma unroll
        for (int mt = 0; mt < 2; mt++) {
            int r0 = m0 + wr * 32 + mt * 16 + gq;
#pragma unroll
            for (int ct = 0; ct < 8; ct++) {
                int n = wc * 64 + ct * 8 + tq * 2;
                if (r0 < M) {
                    __nv_bfloat162 h = __floats2bfloat162_rn(acc[mt][ct][0], acc[mt][ct][1]);
                    ylh[r0 * 64 + (n >> 1)] = *reinterpret_cast<unsigned*>(&h);
                }
                if (r0 + 8 < M) {
                    __nv_bfloat162 h = __floats2bfloat162_rn(acc[mt][ct][2], acc[mt][ct][3]);
                    ylh[(r0 + 8) * 64 + (n >> 1)] = *reinterpret_cast<unsigned*>(&h);
                }
            }
        }
    } else {
        int osel = (yb == 1) ? osel1 : osel2;
        float* C = reinterpret_cast<float*>(buf_ptr(osel));
#pragma unroll
        for (int mt = 0; mt < 2; mt++) {
            int r0 = m0 + wr * 32 + mt * 16 + gq;
#pragma unroll
            for (int ct = 0; ct < 8; ct++) {
                int n = wc * 64 + ct * 8 + tq * 2;
                float b0v = 0.f, b1v = 0.f;
                if (bp != nullptr) { b0v = bp[n]; b1v = bp[n + 1]; }
                if (r0 < M) {
                    float2 o = make_float2(acc[mt][ct][0] + b0v, acc[mt][ct][1] + b1v);
                    *(float2*)&C[(size_t)r0 * 128 + n] = o;
                }
                if (r0 + 8 < M) {
                    float2 o = make_float2(acc[mt][ct][2] + b0v, acc[mt][ct][3] + b1v);
                    *(float2*)&C[(size_t)(r0 + 8) * 128 + n] = o;
                }
            }
        }
    }
}

// ---------------- aggregation (bf16 gather) + BN + ReLU + residual (+ fused out) ------
__global__ __launch_bounds__(256) void k_agg(
    int n0, int n1,
    int res_sel, int out_sel,
    const float* __restrict__ bn_g, const float* __restrict__ bn_b,
    const float* __restrict__ bn_m, const float* __restrict__ bn_v,
    int do_out,
    const float* __restrict__ Wl2, const float* __restrict__ Wr2,
    const float* __restrict__ bl2)
{
    const uint2*  __restrict__ ylh = g_ylh;
    const float4* __restrict__ yr  = g_yr;
    const float4* __restrict__ res = buf_ptr(res_sel);
    float4* __restrict__ out       = buf_ptr(out_sel);
    const int* __restrict__ col    = g_col;

    int w = n0 + ((blockIdx.x * blockDim.x + threadIdx.x) >> 5);
    int lane = threadIdx.x & 31;
    if (w >= n1) return;
    int s0 = g_rowptr[w], s1 = g_rowptr[w + 1];

    float ax = 0.f, ay = 0.f, az = 0.f, aw = 0.f;
    int e = s0;
    for (; e + 7 < s1; e += 8) {
        uint2 p[8];
#pragma unroll
        for (int u = 0; u < 8; u++) {
            int s = clamp_node(col[e + u]);
            p[u] = ylh[s * 32 + lane];
        }
#pragma unroll
        for (int u = 0; u < 8; u++) {
            float2 f0 = __bfloat1622float2(*reinterpret_cast<__nv_bfloat162*>(&p[u].x));
            float2 f1 = __bfloat1622float2(*reinterpret_cast<__nv_bfloat162*>(&p[u].y));
            ax += f0.x; ay += f0.y; az += f1.x; aw += f1.y;
        }
    }
    for (; e < s1; e++) {
        int s = clamp_node(col[e]);
        uint2 p = ylh[s * 32 + lane];
        float2 f0 = __bfloat1622float2(*reinterpret_cast<__nv_bfloat162*>(&p.x));
        float2 f1 = __bfloat1622float2(*reinterpret_cast<__nv_bfloat162*>(&p.y));
        ax += f0.x; ay += f0.y; az += f1.x; aw += f1.y;
    }

    int deg = s1 - s0;
    float inv = 1.f / (float)(deg > 1 ? deg : 1);
    float4 r = yr[w * 32 + lane];
    int f = lane * 4;
    float gx = bn_g[f], gy = bn_g[f + 1], gz = bn_g[f + 2], gw = bn_g[f + 3];
    float bx = bn_b[f], by = bn_b[f + 1], bz = bn_b[f + 2], bw = bn_b[f + 3];
    float mx = bn_m[f], my = bn_m[f + 1], mz = bn_m[f + 2], mw = bn_m[f + 3];
    float qx = bn_v[f], qy = bn_v[f + 1], qz = bn_v[f + 2], qw = bn_v[f + 3];
    float4 rr = res[w * 32 + lane];

    float sx = gx * rsqrtf(qx + BN_EPS);
    float sy = gy * rsqrtf(qy + BN_EPS);
    float sz = gz * rsqrtf(qz + BN_EPS);
    float sw = gw * rsqrtf(qw + BN_EPS);

    float vx = (ax * inv + r.x - mx) * sx + bx;
    float vy = (ay * inv + r.y - my) * sy + by;
    float vz = (az * inv + r.z - mz) * sz + bz;
    float vw = (aw * inv + r.w - mw) * sw + bw;
    vx = fmaxf(vx, 0.f) + rr.x;
    vy = fmaxf(vy, 0.f) + rr.y;
    vz = fmaxf(vz, 0.f) + rr.z;
    vw = fmaxf(vw, 0.f) + rr.w;

    out[w * 32 + lane] = make_float4(vx, vy, vz, vw);

    if (do_out) {
        float a0 = Wl2[f], a1 = Wl2[f + 1], a2 = Wl2[f + 2], a3 = Wl2[f + 3];
        float b0 = Wl2[128 + f], b1 = Wl2[128 + f + 1], b2 = Wl2[128 + f + 2], b3 = Wl2[128 + f + 3];
        float c0 = Wr2[f], c1 = Wr2[f + 1], c2 = Wr2[f + 2], c3 = Wr2[f + 3];
        float e0 = Wr2[128 + f], e1 = Wr2[128 + f + 1], e2 = Wr2[128 + f + 2], e3 = Wr2[128 + f + 3];
        float d0 = vx * a0 + vy * a1 + vz * a2 + vw * a3;
        float d1 = vx * b0 + vy * b1 + vz * b2 + vw * b3;
        float d2 = vx * c0 + vy * c1 + vz * c2 + vw * c3;
        float d3 = vx * e0 + vy * e1 + vz * e2 + vw * e3;
#pragma unroll
        for (int off = 16; off; off >>= 1) {
            d0 += __shfl_xor_sync(0xffffffffu, d0, off);
            d1 += __shfl_xor_sync(0xffffffffu, d1, off);
            d2 += __shfl_xor_sync(0xffffffffu, d2, off);
            d3 += __shfl_xor_sync(0xffffffffu, d3, off);
        }
        if (lane == 0) {
            g_y2[w] = make_float4(d0, d1, d2 + bl2[0], d3 + bl2[1]);
        }
    }
}

// ---------------- final: aggregate 2-wide logits + root term ----------------
__global__ void k_final(float* __restrict__ out)
{
    int i = blockIdx.x * blockDim.x + threadIdx.x;
    if (i >= NN) return;
    int s0 = g_rowptr[i], s1 = g_rowptr[i + 1];
    float a0 = 0.f, a1 = 0.f;
    int e = s0;
    for (; e + 3 < s1; e += 4) {
        float4 v0 = g_y2[clamp_node(g_col[e])];
        float4 v1 = g_y2[clamp_node(g_col[e + 1])];
        float4 v2 = g_y2[clamp_node(g_col[e + 2])];
        float4 v3 = g_y2[clamp_node(g_col[e + 3])];
        a0 += v0.x + v1.x + v2.x + v3.x;
        a1 += v0.y + v1.y + v2.y + v3.y;
    }
    for (; e < s1; e++) {
        float4 v = g_y2[clamp_node(g_col[e])];
        a0 += v.x;
        a1 += v.y;
    }
    int deg = s1 - s0;
    float inv = 1.f / (float)(deg > 1 ? deg : 1);
    float4 self = g_y2[i];
    out[2 * i + 0] = a0 * inv + self.z;
    out[2 * i + 1] = a1 * inv + self.w;
}

// ---------------- launch ----------------
extern "C" void kernel_launch(void* const* d_in, const int* in_sizes, int n_in,
                              void* d_out, int out_size)
{
    const float* x     = (const float*)d_in[0];
    const void*  ei    = (const void*)d_in[1];
    const float* Wl0   = (const float*)d_in[2];
    const float* bl0   = (const float*)d_in[3];
    const float* Wr0   = (const float*)d_in[4];
    const float* Wl1   = (const float*)d_in[5];
    const float* bl1   = (const float*)d_in[6];
    const float* Wr1   = (const float*)d_in[7];
    const float* Wl2   = (const float*)d_in[8];
    const float* bl2   = (const float*)d_in[9];
    const float* Wr2   = (const float*)d_in[10];
    const float* Wres0 = (const float*)d_in[11];
    const float* bn0_g = (const float*)d_in[12];
    const float* bn0_b = (const float*)d_in[13];
    const float* bn0_m = (const float*)d_in[14];
    const float* bn0_v = (const float*)d_in[15];
    const float* bn1_g = (const float*)d_in[16];
    const float* bn1_b = (const float*)d_in[17];
    const float* bn1_m = (const float*)d_in[18];
    const float* bn1_v = (const float*)d_in[19];

    const int off0l = 0;
    const int off0r = S0;
    const int off0s = 2 * S0;
    const int off1l = 3 * S0;
    const int off1r = 3 * S0 + S1;

    cudaStream_t s2;
    cudaStreamCreateWithFlags(&s2, cudaStreamNonBlocking);
    cudaEvent_t evFork, evDense, evCSR, evHalf1;
    cudaEventCreateWithFlags(&evFork,  cudaEventDisableTiming);
    cudaEventCreateWithFlags(&evDense, cudaEventDisableTiming);
    cudaEventCreateWithFlags(&evCSR,   cudaEventDisableTiming);
    cudaEventCreateWithFlags(&evHalf1, cudaEventDisableTiming);

    // fork
    cudaEventRecord(evFork, 0);
    cudaStreamWaitEvent(s2, evFork, 0);

    // ---- CSR branch (default) ----
    e_cvt_hist<<<(NE + 255) / 256, 256>>>(ei);
    k_scan1<<<SCAN_NB, 256>>>();
    k_scan23<<<SCAN_NB, 256>>>();
    k_scatter<<<(NE + 255) / 256, 256>>>();
    cudaEventRecord(evCSR, 0);

    // ---- dense branch (s2): fused transpose + layer-0 triple GEMM ----
    int ttotal = 3 * S0 + 2 * S1;
    k_transpose_all<<<(ttotal + 255) / 256, 256, 0, s2>>>(Wl0, Wr0, Wres0, Wl1, Wr1);
    int gx_all = (NN + 127) / 128;
    k_gemm_tc<<<dim3(gx_all, 3), 256, 0, s2>>>(x, -1, 0, off0l, off0r, off0s,
                                               BUF_YR, BUF_RES, bl0, NN, IN_DIM);
    cudaEventRecord(evDense, s2);

    // cross joins
    cudaStreamWaitEvent(0, evDense, 0);
    cudaStreamWaitEvent(s2, evCSR, 0);

    // ---- pipelined layer-0 agg + layer-1 GEMM, split by node halves ----
    int blk_h0 = (H0 * 32 + 255) / 256;
    int blk_h1 = ((NN - H0) * 32 + 255) / 256;
    int gx_h0 = H0 / 128;
    int gx_h1 = (NN - H0 + 127) / 128;

    k_agg<<<blk_h0, 256>>>(0, H0, BUF_RES, BUF_H1, bn0_g, bn0_b, bn0_m, bn0_v,
                           0, nullptr, nullptr, nullptr);
    k_gemm_tc<<<dim3(gx_h0, 2), 256>>>(nullptr, BUF_H1, 0, off1l, off1r, off1r,
                                       BUF_YR, BUF_YR, bl1, NN, HID);
    k_agg<<<blk_h1, 256, 0, s2>>>(H0, NN, BUF_RES, BUF_H1, bn0_g, bn0_b, bn0_m, bn0_v,
                                  0, nullptr, nullptr, nullptr);
    k_gemm_tc<<<dim3(gx_h1, 2), 256, 0, s2>>>(nullptr, BUF_H1, H0, off1l, off1r, off1r,
                                              BUF_YR, BUF_YR, bl1, NN, HID);
    cudaEventRecord(evHalf1, s2);
    cudaStreamWaitEvent(0, evHalf1, 0);

    // ---- layer-1 aggregate + fused output layer, then final ----
    int blk_all = (NN * 32 + 255) / 256;
    k_agg<<<blk_all, 256>>>(0, NN, BUF_H1, BUF_H2, bn1_g, bn1_b, bn1_m, bn1_v,
                            1, Wl2, Wr2, bl2);
    k_final<<<(NN + 255) / 256, 256>>>((float*)d_out);
}

// round 11
// speedup vs baseline: 2.2592x; 1.0752x over previous
#include <cuda_runtime.h>
#include <cuda_bf16.h>

#define NN 50000
#define NE 800000
#define IN_DIM 166
#define HID 128
#define BN_EPS 1e-5f
#define SCAN_NB 196   // ceil(NN/256)
#define H0 25088      // node split point (multiple of 128)

// ---------------- scratch ----------------
__device__ int    g_deg[NN];           // statically zero-init; scan1 re-zeroes after use
__device__ int    g_rowptr[NN + 1];
__device__ int    g_cursor[NN];
__device__ int    g_bsum[SCAN_NB];
__device__ int    g_src[NE];
__device__ int    g_dst[NE];
__device__ int    g_col[NE];
__device__ uint2  g_ylh[NN * 32];      // [NN,128] bf16 gather table — 256 B/row
__device__ float4 g_yr[NN * 32];
__device__ float4 g_res[NN * 32];
__device__ float4 g_h1[NN * 32];
__device__ float4 g_h2[NN * 32];
__device__ float4 g_y2[NN];
__device__ float4 g_wt[(3 * IN_DIM * HID + 2 * HID * HID) / 4];

#define BUF_YR  1
#define BUF_RES 2
#define BUF_H1  3
#define BUF_H2  4
__device__ __forceinline__ float4* buf_ptr(int s) {
    switch (s) {
        case BUF_YR:  return g_yr;
        case BUF_RES: return g_res;
        case BUF_H1:  return g_h1;
        default:      return g_h2;
    }
}

__device__ __forceinline__ int clamp_node(int v) {
    return v < 0 ? 0 : (v >= NN ? NN - 1 : v);
}

// ---------------- tf32 helpers ----------------
__device__ __forceinline__ unsigned f2tf32(float f) {
    unsigned r;
    asm("cvt.rna.tf32.f32 %0, %1;" : "=r"(r) : "f"(f));
    return r;
}
__device__ __forceinline__ void mma_tf32(float c[4], const unsigned a[4],
                                         unsigned b0, unsigned b1) {
    asm("mma.sync.aligned.m16n8k8.row.col.f32.tf32.tf32.f32 "
        "{%0,%1,%2,%3}, {%4,%5,%6,%7}, {%8,%9}, {%0,%1,%2,%3};"
        : "+f"(c[0]), "+f"(c[1]), "+f"(c[2]), "+f"(c[3])
        : "r"(a[0]), "r"(a[1]), "r"(a[2]), "r"(a[3]), "r"(b0), "r"(b1));
}

// ---------------- edge conversion + inline dtype detect + fused degree histogram ------
__global__ void e_cvt_hist(const void* __restrict__ ei) {
    __shared__ int sh_is64;
    if (threadIdx.x == 0) {
        const int* w = (const int*)ei;
        int all_zero = 1;
        for (int t = 0; t < 32; t++) {
            if (w[2 * t + 1] != 0) { all_zero = 0; break; }
        }
        sh_is64 = all_zero;
    }
    __syncthreads();
    int is64 = sh_is64;
    int i = blockIdx.x * blockDim.x + threadIdx.x;
    if (i < NE) {
        int s, d;
        if (is64) {
            s = (int)((const long long*)ei)[i];
            d = (int)((const long long*)ei)[NE + i];
        } else {
            s = ((const int*)ei)[i];
            d = ((const int*)ei)[NE + i];
        }
        s = clamp_node(s);
        d = clamp_node(d);
        g_src[i] = s;
        g_dst[i] = d;
        atomicAdd(&g_deg[d], 1);
    }
}

// ---------------- CSR scan ----------------
__global__ void k_scan1() {
    __shared__ int sm[256];
    int b = blockIdx.x, t = threadIdx.x;
    int i = b * 256 + t;
    int v = (i < NN) ? g_deg[i] : 0;
    if (i < NN) g_deg[i] = 0;   // restore zeros for the next replay
    sm[t] = v;
    __syncthreads();
    for (int off = 1; off < 256; off <<= 1) {
        int u = (t >= off) ? sm[t - off] : 0;
        __syncthreads();
        sm[t] += u;
        __syncthreads();
    }
    if (i < NN) g_rowptr[i] = sm[t] - v;
    if (t == 255) g_bsum[b] = sm[255];
}

__global__ void k_scan23() {
    __shared__ int sm[256];
    int t = threadIdx.x;
    int b = blockIdx.x;
    int v = (t < SCAN_NB) ? g_bsum[t] : 0;
    sm[t] = v;
    __syncthreads();
    for (int off = 1; off < 256; off <<= 1) {
        int u = (t >= off) ? sm[t - off] : 0;
        __syncthreads();
        sm[t] += u;
        __syncthreads();
    }
    __shared__ int sh_boff;
    if (t == 0) sh_boff = sm[b] - g_bsum[b];
    __syncthreads();
    int boff = sh_boff;
    int i = b * 256 + t;
    if (i < NN) {
        int r = g_rowptr[i] + boff;
        g_rowptr[i] = r;
        g_cursor[i] = r;
    }
    if (i == 0) g_rowptr[NN] = NE;
}

__global__ void k_scatter() {
    int i = blockIdx.x * blockDim.x + threadIdx.x;
    if (i < NE) {
        int pos = atomicAdd(&g_cursor[g_dst[i]], 1);
        if (pos >= 0 && pos < NE) g_col[pos] = g_src[i];
    }
}

// ---------------- fused weight transpose ----------------
#define S0 (HID * IN_DIM)   // 21248
#define S1 (HID * HID)      // 16384

__global__ void k_transpose_all(
    const float* __restrict__ Wl0, const float* __restrict__ Wr0,
    const float* __restrict__ Wres0,
    const float* __restrict__ Wl1, const float* __restrict__ Wr1)
{
    float* wt = reinterpret_cast<float*>(g_wt);
    int i = blockIdx.x * blockDim.x + threadIdx.x;
    if (i < 3 * S0) {
        const float* W = (i < S0) ? Wl0 : (i < 2 * S0) ? Wr0 : Wres0;
        int seg = i / S0;
        int j = i - seg * S0;
        int n = j / IN_DIM, k = j % IN_DIM;
        wt[seg * S0 + k * HID + n] = W[j];
    } else {
        int j = i - 3 * S0;
        if (j < 2 * S1) {
            const float* W = (j < S1) ? Wl1 : Wr1;
            int seg = j / S1;
            int jj = j - seg * S1;
            int n = jj / HID, k = jj % HID;
            wt[3 * S0 + seg * S1 + k * HID + n] = W[jj];
        }
    }
}

// ---------------- tf32 tensor-core GEMM with register-prefetch double buffering ------
// yb == 0 writes packed bf16 to g_ylh (the gather table); yb >= 1 writes fp32.
#define AS_ST 20
#define BS_ST 136

__global__ __launch_bounds__(256) void k_gemm_tc(
    const float* __restrict__ Ax,
    int a_sel, int m_base,
    int woff0, int woff1, int woff2,
    int osel1, int osel2,
    const float* __restrict__ bias,    // applied only for blockIdx.y == 1
    int M, int K)
{
    __shared__ unsigned As[128 * AS_ST];
    __shared__ unsigned Bs[16 * BS_ST];

    int yb = blockIdx.y;
    int woff = (yb == 0) ? woff0 : (yb == 1) ? woff1 : woff2;
    const float* bp = (yb == 1) ? bias : nullptr;

    const float* A = (a_sel < 0) ? Ax : reinterpret_cast<const float*>(buf_ptr(a_sel));
    const float* Wt = reinterpret_cast<const float*>(g_wt) + woff;

    int tid = threadIdx.x;
    int lane = tid & 31, wid = tid >> 5;
    int wr = wid & 3, wc = wid >> 2;
    int m0 = m_base + blockIdx.x * 128;
    int gq = lane >> 2, tq = lane & 3;

    float acc[2][8][4];
#pragma unroll
    for (int mt = 0; mt < 2; mt++)
#pragma unroll
        for (int ct = 0; ct < 8; ct++)
#pragma unroll
            for (int j = 0; j < 4; j++) acc[mt][ct][j] = 0.f;

    float a_reg[8], b_reg[8];
    auto load_tile = [&](int kt) {
        int k0 = kt * 16;
#pragma unroll
        for (int i = 0; i < 8; i++) {
            int l = tid + i * 256;
            int k = l & 15, m = l >> 4;
            float v = 0.f;
            int gm = m0 + m, gk = k0 + k;
            if (gm < M && gk < K) v = A[(size_t)gm * K + gk];
            a_reg[i] = v;
        }
#pragma unroll
        for (int i = 0; i < 8; i++) {
            int l = tid + i * 256;
            int n = l & 127, k = l >> 7;
            float v = 0.f;
            int gk = k0 + k;
            if (gk < K) v = Wt[(size_t)gk * 128 + n];
            b_reg[i] = v;
        }
    };

    int KT = (K + 15) >> 4;
    load_tile(0);
    for (int kt = 0; kt < KT; kt++) {
        // store current tile (convert to tf32 at STS time)
#pragma unroll
        for (int i = 0; i < 8; i++) {
            int l = tid + i * 256;
            int k = l & 15, m = l >> 4;
            As[m * AS_ST + k] = f2tf32(a_reg[i]);
        }
#pragma unroll
        for (int i = 0; i < 8; i++) {
            int l = tid + i * 256;
            int n = l & 127, k = l >> 7;
            Bs[k * BS_ST + n] = f2tf32(b_reg[i]);
        }
        __syncthreads();
        // prefetch next tile into registers: global-load latency overlaps the MMAs below
        if (kt + 1 < KT) load_tile(kt + 1);
#pragma unroll
        for (int ks = 0; ks < 16; ks += 8) {
            unsigned af[2][4];
#pragma unroll
            for (int mt = 0; mt < 2; mt++) {
                int mb = wr * 32 + mt * 16;
                af[mt][0] = As[(mb + gq) * AS_ST + ks + tq];
                af[mt][1] = As[(mb + gq + 8) * AS_ST + ks + tq];
                af[mt][2] = As[(mb + gq) * AS_ST + ks + tq + 4];
                af[mt][3] = As[(mb + gq + 8) * AS_ST + ks + tq + 4];
            }
#pragma unroll
            for (int ct = 0; ct < 8; ct++) {
                int nb = wc * 64 + ct * 8;
                unsigned b0 = Bs[(ks + tq) * BS_ST + nb + gq];
                unsigned b1 = Bs[(ks + tq + 4) * BS_ST + nb + gq];
                mma_tf32(acc[0][ct], af[0], b0, b1);
                mma_tf32(acc[1][ct], af[1], b0, b1);
            }
        }
        __syncthreads();
    }

    if (yb == 0) {
        unsigned* ylh = reinterpret_cast<unsigned*>(g_ylh);
#pragma unroll
        for (int mt = 0; mt < 2; mt++) {
            int r0 = m0 + wr * 32 + mt * 16 + gq;
#pragma unroll
            for (int ct = 0; ct < 8; ct++) {
                int n = wc * 64 + ct * 8 + tq * 2;
                if (r0 < M) {
                    __nv_bfloat162 h = __floats2bfloat162_rn(acc[mt][ct][0], acc[mt][ct][1]);
                    ylh[r0 * 64 + (n >> 1)] = *reinterpret_cast<unsigned*>(&h);
                }
                if (r0 + 8 < M) {
                    __nv_bfloat162 h = __floats2bfloat162_rn(acc[mt][ct][2], acc[mt][ct][3]);
                    ylh[(r0 + 8) * 64 + (n >> 1)] = *reinterpret_cast<unsigned*>(&h);
                }
            }
        }
    } else {
        int osel = (yb == 1) ? osel1 : osel2;
        float* C = reinterpret_cast<float*>(buf_ptr(osel));
#pragma unroll
        for (int mt = 0; mt < 2; mt++) {
            int r0 = m0 + wr * 32 + mt * 16 + gq;
#pragma unroll
            for (int ct = 0; ct < 8; ct++) {
                int n = wc * 64 + ct * 8 + tq * 2;
                float b0v = 0.f, b1v = 0.f;
                if (bp != nullptr) { b0v = bp[n]; b1v = bp[n + 1]; }
                if (r0 < M) {
                    float2 o = make_float2(acc[mt][ct][0] + b0v, acc[mt][ct][1] + b1v);
                    *(float2*)&C[(size_t)r0 * 128 + n] = o;
                }
                if (r0 + 8 < M) {
                    float2 o = make_float2(acc[mt][ct][2] + b0v, acc[mt][ct][3] + b1v);
                    *(float2*)&C[(size_t)(r0 + 8) * 128 + n] = o;
                }
            }
        }
    }
}

// ---------------- aggregation (bf16 gather) + BN + ReLU + residual (+ fused out) ------
__global__ __launch_bounds__(256) void k_agg(
    int n0, int n1,
    int res_sel, int out_sel,
    const float* __restrict__ bn_g, const float* __restrict__ bn_b,
    const float* __restrict__ bn_m, const float* __restrict__ bn_v,
    int do_out,
    const float* __restrict__ Wl2, const float* __restrict__ Wr2,
    const float* __restrict__ bl2)
{
    const uint2*  __restrict__ ylh = g_ylh;
    const float4* __restrict__ yr  = g_yr;
    const float4* __restrict__ res = buf_ptr(res_sel);
    float4* __restrict__ out       = buf_ptr(out_sel);
    const int* __restrict__ col    = g_col;

    int w = n0 + ((blockIdx.x * blockDim.x + threadIdx.x) >> 5);
    int lane = threadIdx.x & 31;
    if (w >= n1) return;
    int s0 = g_rowptr[w], s1 = g_rowptr[w + 1];

    float ax = 0.f, ay = 0.f, az = 0.f, aw = 0.f;
    int e = s0;
    for (; e + 7 < s1; e += 8) {
        uint2 p[8];
#pragma unroll
        for (int u = 0; u < 8; u++) {
            int s = clamp_node(col[e + u]);
            p[u] = ylh[s * 32 + lane];
        }
#pragma unroll
        for (int u = 0; u < 8; u++) {
            float2 f0 = __bfloat1622float2(*reinterpret_cast<__nv_bfloat162*>(&p[u].x));
            float2 f1 = __bfloat1622float2(*reinterpret_cast<__nv_bfloat162*>(&p[u].y));
            ax += f0.x; ay += f0.y; az += f1.x; aw += f1.y;
        }
    }
    for (; e < s1; e++) {
        int s = clamp_node(col[e]);
        uint2 p = ylh[s * 32 + lane];
        float2 f0 = __bfloat1622float2(*reinterpret_cast<__nv_bfloat162*>(&p.x));
        float2 f1 = __bfloat1622float2(*reinterpret_cast<__nv_bfloat162*>(&p.y));
        ax += f0.x; ay += f0.y; az += f1.x; aw += f1.y;
    }

    int deg = s1 - s0;
    float inv = 1.f / (float)(deg > 1 ? deg : 1);
    float4 r = yr[w * 32 + lane];
    int f = lane * 4;
    float gx = bn_g[f], gy = bn_g[f + 1], gz = bn_g[f + 2], gw = bn_g[f + 3];
    float bx = bn_b[f], by = bn_b[f + 1], bz = bn_b[f + 2], bw = bn_b[f + 3];
    float mx = bn_m[f], my = bn_m[f + 1], mz = bn_m[f + 2], mw = bn_m[f + 3];
    float qx = bn_v[f], qy = bn_v[f + 1], qz = bn_v[f + 2], qw = bn_v[f + 3];
    float4 rr = res[w * 32 + lane];

    float sx = gx * rsqrtf(qx + BN_EPS);
    float sy = gy * rsqrtf(qy + BN_EPS);
    float sz = gz * rsqrtf(qz + BN_EPS);
    float sw = gw * rsqrtf(qw + BN_EPS);

    float vx = (ax * inv + r.x - mx) * sx + bx;
    float vy = (ay * inv + r.y - my) * sy + by;
    float vz = (az * inv + r.z - mz) * sz + bz;
    float vw = (aw * inv + r.w - mw) * sw + bw;
    vx = fmaxf(vx, 0.f) + rr.x;
    vy = fmaxf(vy, 0.f) + rr.y;
    vz = fmaxf(vz, 0.f) + rr.z;
    vw = fmaxf(vw, 0.f) + rr.w;

    out[w * 32 + lane] = make_float4(vx, vy, vz, vw);

    if (do_out) {
        float a0 = Wl2[f], a1 = Wl2[f + 1], a2 = Wl2[f + 2], a3 = Wl2[f + 3];
        float b0 = Wl2[128 + f], b1 = Wl2[128 + f + 1], b2 = Wl2[128 + f + 2], b3 = Wl2[128 + f + 3];
        float c0 = Wr2[f], c1 = Wr2[f + 1], c2 = Wr2[f + 2], c3 = Wr2[f + 3];
        float e0 = Wr2[128 + f], e1 = Wr2[128 + f + 1], e2 = Wr2[128 + f + 2], e3 = Wr2[128 + f + 3];
        float d0 = vx * a0 + vy * a1 + vz * a2 + vw * a3;
        float d1 = vx * b0 + vy * b1 + vz * b2 + vw * b3;
        float d2 = vx * c0 + vy * c1 + vz * c2 + vw * c3;
        float d3 = vx * e0 + vy * e1 + vz * e2 + vw * e3;
#pragma unroll
        for (int off = 16; off; off >>= 1) {
            d0 += __shfl_xor_sync(0xffffffffu, d0, off);
            d1 += __shfl_xor_sync(0xffffffffu, d1, off);
            d2 += __shfl_xor_sync(0xffffffffu, d2, off);
            d3 += __shfl_xor_sync(0xffffffffu, d3, off);
        }
        if (lane == 0) {
            g_y2[w] = make_float4(d0, d1, d2 + bl2[0], d3 + bl2[1]);
        }
    }
}

// ---------------- final: aggregate 2-wide logits + root term ----------------
__global__ void k_final(float* __restrict__ out)
{
    int i = blockIdx.x * blockDim.x + threadIdx.x;
    if (i >= NN) return;
    int s0 = g_rowptr[i], s1 = g_rowptr[i + 1];
    float a0 = 0.f, a1 = 0.f;
    int e = s0;
    for (; e + 3 < s1; e += 4) {
        float4 v0 = g_y2[clamp_node(g_col[e])];
        float4 v1 = g_y2[clamp_node(g_col[e + 1])];
        float4 v2 = g_y2[clamp_node(g_col[e + 2])];
        float4 v3 = g_y2[clamp_node(g_col[e + 3])];
        a0 += v0.x + v1.x + v2.x + v3.x;
        a1 += v0.y + v1.y + v2.y + v3.y;
    }
    for (; e < s1; e++) {
        float4 v = g_y2[clamp_node(g_col[e])];
        a0 += v.x;
        a1 += v.y;
    }
    int deg = s1 - s0;
    float inv = 1.f / (float)(deg > 1 ? deg : 1);
    float4 self = g_y2[i];
    out[2 * i + 0] = a0 * inv + self.z;
    out[2 * i + 1] = a1 * inv + self.w;
}

// ---------------- launch ----------------
extern "C" void kernel_launch(void* const* d_in, const int* in_sizes, int n_in,
                              void* d_out, int out_size)
{
    const float* x     = (const float*)d_in[0];
    const void*  ei    = (const void*)d_in[1];
    const float* Wl0   = (const float*)d_in[2];
    const float* bl0   = (const float*)d_in[3];
    const float* Wr0   = (const float*)d_in[4];
    const float* Wl1   = (const float*)d_in[5];
    const float* bl1   = (const float*)d_in[6];
    const float* Wr1   = (const float*)d_in[7];
    const float* Wl2   = (const float*)d_in[8];
    const float* bl2   = (const float*)d_in[9];
    const float* Wr2   = (const float*)d_in[10];
    const float* Wres0 = (const float*)d_in[11];
    const float* bn0_g = (const float*)d_in[12];
    const float* bn0_b = (const float*)d_in[13];
    const float* bn0_m = (const float*)d_in[14];
    const float* bn0_v = (const float*)d_in[15];
    const float* bn1_g = (const float*)d_in[16];
    const float* bn1_b = (const float*)d_in[17];
    const float* bn1_m = (const float*)d_in[18];
    const float* bn1_v = (const float*)d_in[19];

    const int off0l = 0;
    const int off0r = S0;
    const int off0s = 2 * S0;
    const int off1l = 3 * S0;
    const int off1r = 3 * S0 + S1;

    cudaStream_t s2;
    cudaStreamCreateWithFlags(&s2, cudaStreamNonBlocking);
    cudaEvent_t evFork, evDense, evCSR, evHalf1;
    cudaEventCreateWithFlags(&evFork,  cudaEventDisableTiming);
    cudaEventCreateWithFlags(&evDense, cudaEventDisableTiming);
    cudaEventCreateWithFlags(&evCSR,   cudaEventDisableTiming);
    cudaEventCreateWithFlags(&evHalf1, cudaEventDisableTiming);

    // fork
    cudaEventRecord(evFork, 0);
    cudaStreamWaitEvent(s2, evFork, 0);

    int gx_all = (NN + 127) / 128;
    int ttotal = 3 * S0 + 2 * S1;

    // enqueue order chosen so gemm0 is host-launch #4 (ncu captures global #6
    // = our #4 given the 2 harness pre-kernels observed in R8-R10)
    e_cvt_hist<<<(NE + 255) / 256, 256>>>(ei);                                     // #1 (stream 0)
    k_scan1<<<SCAN_NB, 256>>>();                                                   // #2 (stream 0)
    k_transpose_all<<<(ttotal + 255) / 256, 256, 0, s2>>>(Wl0, Wr0, Wres0, Wl1, Wr1); // #3 (s2)
    k_gemm_tc<<<dim3(gx_all, 3), 256, 0, s2>>>(x, -1, 0, off0l, off0r, off0s,
                                               BUF_YR, BUF_RES, bl0, NN, IN_DIM);  // #4 (s2)
    cudaEventRecord(evDense, s2);
    k_scan23<<<SCAN_NB, 256>>>();                                                  // #5 (stream 0)
    k_scatter<<<(NE + 255) / 256, 256>>>();                                        // #6 (stream 0)
    cudaEventRecord(evCSR, 0);

    // cross joins
    cudaStreamWaitEvent(0, evDense, 0);
    cudaStreamWaitEvent(s2, evCSR, 0);

    // ---- pipelined layer-0 agg + layer-1 GEMM, split by node halves ----
    int blk_h0 = (H0 * 32 + 255) / 256;
    int blk_h1 = ((NN - H0) * 32 + 255) / 256;
    int gx_h0 = H0 / 128;
    int gx_h1 = (NN - H0 + 127) / 128;

    k_agg<<<blk_h0, 256>>>(0, H0, BUF_RES, BUF_H1, bn0_g, bn0_b, bn0_m, bn0_v,
                           0, nullptr, nullptr, nullptr);
    k_gemm_tc<<<dim3(gx_h0, 2), 256>>>(nullptr, BUF_H1, 0, off1l, off1r, off1r,
                                       BUF_YR, BUF_YR, bl1, NN, HID);
    k_agg<<<blk_h1, 256, 0, s2>>>(H0, NN, BUF_RES, BUF_H1, bn0_g, bn0_b, bn0_m, bn0_v,
                                  0, nullptr, nullptr, nullptr);
    k_gemm_tc<<<dim3(gx_h1, 2), 256, 0, s2>>>(nullptr, BUF_H1, H0, off1l, off1r, off1r,
                                              BUF_YR, BUF_YR, bl1, NN, HID);
    cudaEventRecord(evHalf1, s2);
    cudaStreamWaitEvent(0, evHalf1, 0);

    // ---- layer-1 aggregate + fused output layer, then final ----
    int blk_all = (NN * 32 + 255) / 256;
    k_agg<<<blk_all, 256>>>(0, NN, BUF_H1, BUF_H2, bn1_g, bn1_b, bn1_m, bn1_v,
                            1, Wl2, Wr2, bl2);
    k_final<<<(NN + 255) / 256, 256>>>((float*)d_out);
}

// round 13
// speedup vs baseline: 2.5711x; 1.1380x over previous
#include <cuda_runtime.h>
#include <cuda_bf16.h>

#define NN 50000
#define NE 800000
#define IN_DIM 166
#define HID 128
#define BN_EPS 1e-5f
#define SCAN_NB 196   // ceil(NN/256)
#define H0 25088      // node split point (multiple of 128)

#define KP0 176                    // padded K for layer 0 (multiple of 16, 16B-aligned rows)
#define W0SZ (KP0 * HID)           // 22528 words per layer-0 weight
#define W1SZ (HID * HID)           // 16384 words per layer-1 weight

// ---------------- scratch ----------------
__device__ int    g_deg[NN];           // statically zero-init; scan1 re-zeroes after use
__device__ int    g_rowptr[NN + 1];
__device__ int    g_cursor[NN];
__device__ int    g_bsum[SCAN_NB];
__device__ int    g_src[NE];
__device__ int    g_dst[NE];
__device__ int    g_col[NE];
__device__ uint2  g_ylh[NN * 32];      // [NN,128] bf16 gather table — 256 B/row
__device__ float4 g_yr[NN * 32];
__device__ float4 g_res[NN * 32];
__device__ float4 g_h1[NN * 32];
__device__ float4 g_h2[NN * 32];
__device__ float4 g_y2[NN];
__device__ uint4  g_xt4[NN * (KP0 / 4)];       // x pre-converted to tf32, padded rows
__device__ uint4  g_h1t4[NN * 32];             // h1 tf32 copy for layer-1 GEMM
__device__ uint4  g_wt4[(3 * W0SZ + 2 * W1SZ) / 4];  // transposed tf32 weights

#define BUF_YR  1
#define BUF_RES 2
#define BUF_H1  3
#define BUF_H2  4
__device__ __forceinline__ float4* buf_ptr(int s) {
    switch (s) {
        case BUF_YR:  return g_yr;
        case BUF_RES: return g_res;
        case BUF_H1:  return g_h1;
        default:      return g_h2;
    }
}

__device__ __forceinline__ int clamp_node(int v) {
    return v < 0 ? 0 : (v >= NN ? NN - 1 : v);
}

// ---------------- tf32 helpers ----------------
__device__ __forceinline__ unsigned f2tf32(float f) {
    unsigned r;
    asm("cvt.rna.tf32.f32 %0, %1;" : "=r"(r) : "f"(f));
    return r;
}
__device__ __forceinline__ void mma_tf32(float c[4], const unsigned a[4],
                                         unsigned b0, unsigned b1) {
    asm("mma.sync.aligned.m16n8k8.row.col.f32.tf32.tf32.f32 "
        "{%0,%1,%2,%3}, {%4,%5,%6,%7}, {%8,%9}, {%0,%1,%2,%3};"
        : "+f"(c[0]), "+f"(c[1]), "+f"(c[2]), "+f"(c[3])
        : "r"(a[0]), "r"(a[1]), "r"(a[2]), "r"(a[3]), "r"(b0), "r"(b1));
}

// ---------------- edge conversion + inline dtype detect + fused degree histogram ------
__global__ void e_cvt_hist(const void* __restrict__ ei) {
    __shared__ int sh_is64;
    if (threadIdx.x == 0) {
        const int* w = (const int*)ei;
        int all_zero = 1;
        for (int t = 0; t < 32; t++) {
            if (w[2 * t + 1] != 0) { all_zero = 0; break; }
        }
        sh_is64 = all_zero;
    }
    __syncthreads();
    int is64 = sh_is64;
    int i = blockIdx.x * blockDim.x + threadIdx.x;
    if (i < NE) {
        int s, d;
        if (is64) {
            s = (int)((const long long*)ei)[i];
            d = (int)((const long long*)ei)[NE + i];
        } else {
            s = ((const int*)ei)[i];
            d = ((const int*)ei)[NE + i];
        }
        s = clamp_node(s);
        d = clamp_node(d);
        g_src[i] = s;
        g_dst[i] = d;
        atomicAdd(&g_deg[d], 1);
    }
}

// ---------------- CSR scan ----------------
__global__ void k_scan1() {
    __shared__ int sm[256];
    int b = blockIdx.x, t = threadIdx.x;
    int i = b * 256 + t;
    int v = (i < NN) ? g_deg[i] : 0;
    if (i < NN) g_deg[i] = 0;   // restore zeros for the next replay
    sm[t] = v;
    __syncthreads();
    for (int off = 1; off < 256; off <<= 1) {
        int u = (t >= off) ? sm[t - off] : 0;
        __syncthreads();
        sm[t] += u;
        __syncthreads();
    }
    if (i < NN) g_rowptr[i] = sm[t] - v;
    if (t == 255) g_bsum[b] = sm[255];
}

__global__ void k_scan23() {
    __shared__ int sm[256];
    int t = threadIdx.x;
    int b = blockIdx.x;
    int v = (t < SCAN_NB) ? g_bsum[t] : 0;
    sm[t] = v;
    __syncthreads();
    for (int off = 1; off < 256; off <<= 1) {
        int u = (t >= off) ? sm[t - off] : 0;
        __syncthreads();
        sm[t] += u;
        __syncthreads();
    }
    __shared__ int sh_boff;
    if (t == 0) sh_boff = sm[b] - g_bsum[b];
    __syncthreads();
    int boff = sh_boff;
    int i = b * 256 + t;
    if (i < NN) {
        int r = g_rowptr[i] + boff;
        g_rowptr[i] = r;
        g_cursor[i] = r;
    }
    if (i == 0) g_rowptr[NN] = NE;
}

__global__ void k_scatter() {
    int i = blockIdx.x * blockDim.x + threadIdx.x;
    if (i < NE) {
        int pos = atomicAdd(&g_cursor[g_dst[i]], 1);
        if (pos >= 0 && pos < NE) g_col[pos] = g_src[i];
    }
}

// ---------------- x -> padded tf32 table ----------------
__global__ void k_xcvt(const float* __restrict__ x) {
    unsigned* xt = reinterpret_cast<unsigned*>(g_xt4);
    int idx = blockIdx.x * blockDim.x + threadIdx.x;
    if (idx < NN * KP0) {
        int row = idx / KP0;
        int k = idx - row * KP0;
        unsigned v = 0;
        if (k < IN_DIM) v = f2tf32(x[row * IN_DIM + k]);
        xt[idx] = v;
    }
}

// ---------------- fused weight transpose -> tf32, layer-0 padded to KP0 rows ---------
__global__ void k_transpose_all(
    const float* __restrict__ Wl0, const float* __restrict__ Wr0,
    const float* __restrict__ Wres0,
    const float* __restrict__ Wl1, const float* __restrict__ Wr1)
{
    unsigned* wt = reinterpret_cast<unsigned*>(g_wt4);
    int i = blockIdx.x * blockDim.x + threadIdx.x;
    if (i < 3 * W0SZ) {
        int seg = i / W0SZ;
        int j = i - seg * W0SZ;
        int k = j >> 7, n = j & 127;
        const float* W = (seg == 0) ? Wl0 : (seg == 1) ? Wr0 : Wres0;
        unsigned v = 0;
        if (k < IN_DIM) v = f2tf32(W[n * IN_DIM + k]);
        wt[i] = v;
    } else if (i < 3 * W0SZ + 2 * W1SZ) {
        int j = i - 3 * W0SZ;
        int seg = j / W1SZ;
        int jj = j - seg * W1SZ;
        int k = jj >> 7, n = jj & 127;
        const float* W = seg ? Wr1 : Wl1;
        wt[i] = f2tf32(W[n * HID + k]);
    }
}

// ---------------- tf32 tensor-core GEMM: cp.async 2-stage pipeline -------------------
// inputs already tf32 in memory; yb==0 writes bf16 gather table, yb>=1 fp32.
#define AS_ST 20
#define BS_ST 136
#define A_WORDS (128 * AS_ST)   // 2560
#define B_WORDS (16 * BS_ST)    // 2176

__global__ __launch_bounds__(256, 2) void k_gemm_tc(
    int a_src,                 // 0 = g_xt4 (KP=176), 1 = g_h1t4 (KP=128)
    int m_base,
    int woff0, int woff1, int woff2,
    int osel1, int osel2,
    const float* __restrict__ bias,   // applied only for blockIdx.y == 1
    int M)
{
    __shared__ __align__(16) unsigned As[2 * A_WORDS];
    __shared__ __align__(16) unsigned Bs[2 * B_WORDS];

    int yb = blockIdx.y;
    int woff = (yb == 0) ? woff0 : (yb == 1) ? woff1 : woff2;
    const float* bp = (yb == 1) ? bias : nullptr;

    const unsigned* AT = a_src ? reinterpret_cast<const unsigned*>(g_h1t4)
                               : reinterpret_cast<const unsigned*>(g_xt4);
    int KP = a_src ? HID : KP0;
    const unsigned* Wt = reinterpret_cast<const unsigned*>(g_wt4) + woff;

    int tid = threadIdx.x;
    int lane = tid & 31, wid = tid >> 5;
    int wr = wid & 3, wc = wid >> 2;
    int m0 = m_base + blockIdx.x * 128;
    int gq = lane >> 2, tq = lane & 3;

    unsigned as_u32 = (unsigned)__cvta_generic_to_shared(As);
    unsigned bs_u32 = (unsigned)__cvta_generic_to_shared(Bs);

    // per-thread load descriptors (kt-invariant)
    int arow[2], akg[2], avalid[2];
    int brow[2], bng[2];
#pragma unroll
    for (int i = 0; i < 2; i++) {
        int c = tid + i * 256;
        arow[i] = c >> 2;  akg[i] = (c & 3) * 4;
        avalid[i] = (m0 + arow[i]) < M;
        brow[i] = c >> 5;  bng[i] = (c & 31) * 4;
    }

    auto stage = [&](int kt, int buf) {
        int k0 = kt << 4;
#pragma unroll
        for (int i = 0; i < 2; i++) {
            unsigned dst = as_u32 + (buf * A_WORDS + arow[i] * AS_ST + akg[i]) * 4u;
            size_t off = avalid[i] ? ((size_t)(m0 + arow[i]) * KP + k0 + akg[i]) : 0;
            int sz = avalid[i] ? 16 : 0;
            asm volatile("cp.async.cg.shared.global [%0], [%1], 16, %2;"
                         :: "r"(dst), "l"(AT + off), "r"(sz));
        }
#pragma unroll
        for (int i = 0; i < 2; i++) {
            unsigned dst = bs_u32 + (buf * B_WORDS + brow[i] * BS_ST + bng[i]) * 4u;
            asm volatile("cp.async.cg.shared.global [%0], [%1], 16;"
                         :: "r"(dst), "l"(Wt + (size_t)(k0 + brow[i]) * 128 + bng[i]));
        }
        asm volatile("cp.async.commit_group;");
    };

    float acc[2][8][4];
#pragma unroll
    for (int mt = 0; mt < 2; mt++)
#pragma unroll
        for (int ct = 0; ct < 8; ct++)
#pragma unroll
            for (int j = 0; j < 4; j++) acc[mt][ct][j] = 0.f;

    int KT = KP >> 4;
    stage(0, 0);
    for (int kt = 0; kt < KT; kt++) {
        int buf = kt & 1;
        if (kt + 1 < KT) {
            stage(kt + 1, buf ^ 1);
            asm volatile("cp.async.wait_group 1;");
        } else {
            asm volatile("cp.async.wait_group 0;");
        }
        __syncthreads();
        const unsigned* Ab = As + buf * A_WORDS;
        const unsigned* Bb = Bs + buf * B_WORDS;
#pragma unroll
        for (int ks = 0; ks < 16; ks += 8) {
            unsigned af[2][4];
#pragma unroll
            for (int mt = 0; mt < 2; mt++) {
                int mb = wr * 32 + mt * 16;
                af[mt][0] = Ab[(mb + gq) * AS_ST + ks + tq];
                af[mt][1] = Ab[(mb + gq + 8) * AS_ST + ks + tq];
                af[mt][2] = Ab[(mb + gq) * AS_ST + ks + tq + 4];
                af[mt][3] = Ab[(mb + gq + 8) * AS_ST + ks + tq + 4];
            }
#pragma unroll
            for (int ct = 0; ct < 8; ct++) {
                int nb = wc * 64 + ct * 8;
                unsigned b0 = Bb[(ks + tq) * BS_ST + nb + gq];
                unsigned b1 = Bb[(ks + tq + 4) * BS_ST + nb + gq];
                mma_tf32(acc[0][ct], af[0], b0, b1);
                mma_tf32(acc[1][ct], af[1], b0, b1);
            }
        }
        __syncthreads();
    }

    if (yb == 0) {
        unsigned* ylh = reinterpret_cast<unsigned*>(g_ylh);
#pragma unroll
        for (int mt = 0; mt < 2; mt++) {
            int r0 = m0 + wr * 32 + mt * 16 + gq;
#pragma unroll
            for (int ct = 0; ct < 8; ct++) {
                int n = wc * 64 + ct * 8 + tq * 2;
                if (r0 < M) {
                    __nv_bfloat162 h = __floats2bfloat162_rn(acc[mt][ct][0], acc[mt][ct][1]);
                    ylh[r0 * 64 + (n >> 1)] = *reinterpret_cast<unsigned*>(&h);
                }
                if (r0 + 8 < M) {
                    __nv_bfloat162 h = __floats2bfloat162_rn(acc[mt][ct][2], acc[mt][ct][3]);
                    ylh[(r0 + 8) * 64 + (n >> 1)] = *reinterpret_cast<unsigned*>(&h);
                }
            }
        }
    } else {
        int osel = (yb == 1) ? osel1 : osel2;
        float* C = reinterpret_cast<float*>(buf_ptr(osel));
#pragma unroll
        for (int mt = 0; mt < 2; mt++) {
            int r0 = m0 + wr * 32 + mt * 16 + gq;
#pragma unroll
            for (int ct = 0; ct < 8; ct++) {
                int n = wc * 64 + ct * 8 + tq * 2;
                float b0v = 0.f, b1v = 0.f;
                if (bp != nullptr) { b0v = bp[n]; b1v = bp[n + 1]; }
                if (r0 < M) {
                    float2 o = make_float2(acc[mt][ct][0] + b0v, acc[mt][ct][1] + b1v);
                    *(float2*)&C[(size_t)r0 * 128 + n] = o;
                }
                if (r0 + 8 < M) {
                    float2 o = make_float2(acc[mt][ct][2] + b0v, acc[mt][ct][3] + b1v);
                    *(float2*)&C[(size_t)(r0 + 8) * 128 + n] = o;
                }
            }
        }
    }
}

// ---------------- aggregation (bf16 gather) + BN + ReLU + residual (+ fused out) ------
__global__ __launch_bounds__(256) void k_agg(
    int n0, int n1,
    int res_sel, int out_sel, int write_t,
    const float* __restrict__ bn_g, const float* __restrict__ bn_b,
    const float* __restrict__ bn_m, const float* __restrict__ bn_v,
    int do_out,
    const float* __restrict__ Wl2, const float* __restrict__ Wr2,
    const float* __restrict__ bl2)
{
    const uint2*  __restrict__ ylh = g_ylh;
    const float4* __restrict__ yr  = g_yr;
    const float4* __restrict__ res = buf_ptr(res_sel);
    float4* __restrict__ out       = buf_ptr(out_sel);
    const int* __restrict__ col    = g_col;

    int w = n0 + ((blockIdx.x * blockDim.x + threadIdx.x) >> 5);
    int lane = threadIdx.x & 31;
    if (w >= n1) return;
    int s0 = g_rowptr[w], s1 = g_rowptr[w + 1];

    float ax = 0.f, ay = 0.f, az = 0.f, aw = 0.f;
    int e = s0;
    for (; e + 7 < s1; e += 8) {
        uint2 p[8];
#pragma unroll
        for (int u = 0; u < 8; u++) {
            int s = clamp_node(col[e + u]);
            p[u] = ylh[s * 32 + lane];
        }
#pragma unroll
        for (int u = 0; u < 8; u++) {
            float2 f0 = __bfloat1622float2(*reinterpret_cast<__nv_bfloat162*>(&p[u].x));
            float2 f1 = __bfloat1622float2(*reinterpret_cast<__nv_bfloat162*>(&p[u].y));
            ax += f0.x; ay += f0.y; az += f1.x; aw += f1.y;
        }
    }
    for (; e < s1; e++) {
        int s = clamp_node(col[e]);
        uint2 p = ylh[s * 32 + lane];
        float2 f0 = __bfloat1622float2(*reinterpret_cast<__nv_bfloat162*>(&p.x));
        float2 f1 = __bfloat1622float2(*reinterpret_cast<__nv_bfloat162*>(&p.y));
        ax += f0.x; ay += f0.y; az += f1.x; aw += f1.y;
    }

    int deg = s1 - s0;
    float inv = 1.f / (float)(deg > 1 ? deg : 1);
    float4 r = yr[w * 32 + lane];
    int f = lane * 4;
    float gx = bn_g[f], gy = bn_g[f + 1], gz = bn_g[f + 2], gw = bn_g[f + 3];
    float bx = bn_b[f], by = bn_b[f + 1], bz = bn_b[f + 2], bw = bn_b[f + 3];
    float mx = bn_m[f], my = bn_m[f + 1], mz = bn_m[f + 2], mw = bn_m[f + 3];
    float qx = bn_v[f], qy = bn_v[f + 1], qz = bn_v[f + 2], qw = bn_v[f + 3];
    float4 rr = res[w * 32 + lane];

    float sx = gx * rsqrtf(qx + BN_EPS);
    float sy = gy * rsqrtf(qy + BN_EPS);
    float sz = gz * rsqrtf(qz + BN_EPS);
    float sw = gw * rsqrtf(qw + BN_EPS);

    float vx = (ax * inv + r.x - mx) * sx + bx;
    float vy = (ay * inv + r.y - my) * sy + by;
    float vz = (az * inv + r.z - mz) * sz + bz;
    float vw = (aw * inv + r.w - mw) * sw + bw;
    vx = fmaxf(vx, 0.f) + rr.x;
    vy = fmaxf(vy, 0.f) + rr.y;
    vz = fmaxf(vz, 0.f) + rr.z;
    vw = fmaxf(vw, 0.f) + rr.w;

    out[w * 32 + lane] = make_float4(vx, vy, vz, vw);

    if (write_t) {
        uint4 t;
        t.x = f2tf32(vx); t.y = f2tf32(vy); t.z = f2tf32(vz); t.w = f2tf32(vw);
        g_h1t4[w * 32 + lane] = t;
    }

    if (do_out) {
        float a0 = Wl2[f], a1 = Wl2[f + 1], a2 = Wl2[f + 2], a3 = Wl2[f + 3];
        float b0 = Wl2[128 + f], b1 = Wl2[128 + f + 1], b2 = Wl2[128 + f + 2], b3 = Wl2[128 + f + 3];
        float c0 = Wr2[f], c1 = Wr2[f + 1], c2 = Wr2[f + 2], c3 = Wr2[f + 3];
        float e0 = Wr2[128 + f], e1 = Wr2[128 + f + 1], e2 = Wr2[128 + f + 2], e3 = Wr2[128 + f + 3];
        float d0 = vx * a0 + vy * a1 + vz * a2 + vw * a3;
        float d1 = vx * b0 + vy * b1 + vz * b2 + vw * b3;
        float d2 = vx * c0 + vy * c1 + vz * c2 + vw * c3;
        float d3 = vx * e0 + vy * e1 + vz * e2 + vw * e3;
#pragma unroll
        for (int off = 16; off; off >>= 1) {
            d0 += __shfl_xor_sync(0xffffffffu, d0, off);
            d1 += __shfl_xor_sync(0xffffffffu, d1, off);
            d2 += __shfl_xor_sync(0xffffffffu, d2, off);
            d3 += __shfl_xor_sync(0xffffffffu, d3, off);
        }
        if (lane == 0) {
            g_y2[w] = make_float4(d0, d1, d2 + bl2[0], d3 + bl2[1]);
        }
    }
}

// ---------------- final: aggregate 2-wide logits + root term ----------------
__global__ void k_final(float* __restrict__ out)
{
    int i = blockIdx.x * blockDim.x + threadIdx.x;
    if (i >= NN) return;
    int s0 = g_rowptr[i], s1 = g_rowptr[i + 1];
    float a0 = 0.f, a1 = 0.f;
    int e = s0;
    for (; e + 3 < s1; e += 4) {
        float4 v0 = g_y2[clamp_node(g_col[e])];
        float4 v1 = g_y2[clamp_node(g_col[e + 1])];
        float4 v2 = g_y2[clamp_node(g_col[e + 2])];
        float4 v3 = g_y2[clamp_node(g_col[e + 3])];
        a0 += v0.x + v1.x + v2.x + v3.x;
        a1 += v0.y + v1.y + v2.y + v3.y;
    }
    for (; e < s1; e++) {
        float4 v = g_y2[clamp_node(g_col[e])];
        a0 += v.x;
        a1 += v.y;
    }
    int deg = s1 - s0;
    float inv = 1.f / (float)(deg > 1 ? deg : 1);
    float4 self = g_y2[i];
    out[2 * i + 0] = a0 * inv + self.z;
    out[2 * i + 1] = a1 * inv + self.w;
}

// ---------------- launch ----------------
extern "C" void kernel_launch(void* const* d_in, const int* in_sizes, int n_in,
                              void* d_out, int out_size)
{
    const float* x     = (const float*)d_in[0];
    const void*  ei    = (const void*)d_in[1];
    const float* Wl0   = (const float*)d_in[2];
    const float* bl0   = (const float*)d_in[3];
    const float* Wr0   = (const float*)d_in[4];
    const float* Wl1   = (const float*)d_in[5];
    const float* bl1   = (const float*)d_in[6];
    const float* Wr1   = (const float*)d_in[7];
    const float* Wl2   = (const float*)d_in[8];
    const float* bl2   = (const float*)d_in[9];
    const float* Wr2   = (const float*)d_in[10];
    const float* Wres0 = (const float*)d_in[11];
    const float* bn0_g = (const float*)d_in[12];
    const float* bn0_b = (const float*)d_in[13];
    const float* bn0_m = (const float*)d_in[14];
    const float* bn0_v = (const float*)d_in[15];
    const float* bn1_g = (const float*)d_in[16];
    const float* bn1_b = (const float*)d_in[17];
    const float* bn1_m = (const float*)d_in[18];
    const float* bn1_v = (const float*)d_in[19];

    const int off0l = 0;
    const int off0r = W0SZ;
    const int off0s = 2 * W0SZ;
    const int off1l = 3 * W0SZ;
    const int off1r = 3 * W0SZ + W1SZ;

    cudaStream_t s2;
    cudaStreamCreateWithFlags(&s2, cudaStreamNonBlocking);
    cudaEvent_t evFork, evDense, evCSR, evHalf1;
    cudaEventCreateWithFlags(&evFork,  cudaEventDisableTiming);
    cudaEventCreateWithFlags(&evDense, cudaEventDisableTiming);
    cudaEventCreateWithFlags(&evCSR,   cudaEventDisableTiming);
    cudaEventCreateWithFlags(&evHalf1, cudaEventDisableTiming);

    // fork
    cudaEventRecord(evFork, 0);
    cudaStreamWaitEvent(s2, evFork, 0);

    int gx_all = (NN + 127) / 128;
    int ttotal = 3 * W0SZ + 2 * W1SZ;
    int xtotal = NN * KP0;

    // enqueue order keeps gemm0 as host-launch #4 (ncu window)
    e_cvt_hist<<<(NE + 255) / 256, 256>>>(ei);                                        // #1 s0
    k_xcvt<<<(xtotal + 255) / 256, 256, 0, s2>>>(x);                                  // #2 s2
    k_transpose_all<<<(ttotal + 255) / 256, 256, 0, s2>>>(Wl0, Wr0, Wres0, Wl1, Wr1); // #3 s2
    k_gemm_tc<<<dim3(gx_all, 3), 256, 0, s2>>>(0, 0, off0l, off0r, off0s,
                                               BUF_YR, BUF_RES, bl0, NN);             // #4 s2
    cudaEventRecord(evDense, s2);
    k_scan1<<<SCAN_NB, 256>>>();                                                      // #5 s0
    k_scan23<<<SCAN_NB, 256>>>();                                                     // #6 s0
    k_scatter<<<(NE + 255) / 256, 256>>>();                                           // #7 s0
    cudaEventRecord(evCSR, 0);

    // cross joins
    cudaStreamWaitEvent(0, evDense, 0);
    cudaStreamWaitEvent(s2, evCSR, 0);

    // ---- pipelined layer-0 agg + layer-1 GEMM, split by node halves ----
    int blk_h0 = (H0 * 32 + 255) / 256;
    int blk_h1 = ((NN - H0) * 32 + 255) / 256;
    int gx_h0 = H0 / 128;
    int gx_h1 = (NN - H0 + 127) / 128;

    k_agg<<<blk_h0, 256>>>(0, H0, BUF_RES, BUF_H1, 1, bn0_g, bn0_b, bn0_m, bn0_v,
                           0, nullptr, nullptr, nullptr);
    k_gemm_tc<<<dim3(gx_h0, 2), 256>>>(1, 0, off1l, off1r, off1r,
                                       BUF_YR, BUF_YR, bl1, NN);
    k_agg<<<blk_h1, 256, 0, s2>>>(H0, NN, BUF_RES, BUF_H1, 1, bn0_g, bn0_b, bn0_m, bn0_v,
                                  0, nullptr, nullptr, nullptr);
    k_gemm_tc<<<dim3(gx_h1, 2), 256, 0, s2>>>(1, H0, off1l, off1r, off1r,
                                              BUF_YR, BUF_YR, bl1, NN);
    cudaEventRecord(evHalf1, s2);
    cudaStreamWaitEvent(0, evHalf1, 0);

    // ---- layer-1 aggregate + fused output layer, then final ----
    int blk_all = (NN * 32 + 255) / 256;
    k_agg<<<blk_all, 256>>>(0, NN, BUF_H1, BUF_H2, 0, bn1_g, bn1_b, bn1_m, bn1_v,
                            1, Wl2, Wr2, bl2);
    k_final<<<(NN + 255) / 256, 256>>>((float*)d_out);
}